// round 12
// baseline (speedup 1.0000x reference)
#include <cuda_runtime.h>
#include <cuda_bf16.h>
#include <cstdint>

#define B_  32
#define N_  1024
#define D_  128
#define NDF (N_*D_)          // 131072 per batch per tensor
#define TOT (B_*N_*D_)       // 4194304
#define NBUCK 4096           // 12-bit monotone-key prefix buckets

// ---------------- device scratch ----------------
__device__ float    g_normP[B_*N_];
__device__ float    g_normT[B_*N_];
__device__ unsigned g_m1[B_*N_];       // min_i d^2 (float bits)
__device__ unsigned g_m2[N_*N_];       // min_b d^2 (float bits)
__device__ double   g_mae, g_s1, g_s2;
__device__ double   g_emd[B_];
__device__ unsigned long long g_hP[B_*NBUCK];   // packed (count<<44 | fixed-point sum)
__device__ unsigned long long g_hG[B_*NBUCK];
__device__ unsigned g_bfP[TOT/2];      // bf16x2 packed pred
__device__ unsigned g_bfG[TOT/2];      // bf16x2 packed target

// ---------------- helpers ----------------
__device__ __forceinline__ unsigned pack_bf16x2(float lo, float hi) {
    unsigned r;
    asm("cvt.rn.bf16x2.f32 %0, %1, %2;" : "=r"(r) : "f"(hi), "f"(lo));
    return r;
}
__device__ __forceinline__ float bf_lo(unsigned u) { return __uint_as_float(u << 16); }
__device__ __forceinline__ float bf_hi(unsigned u) { return __uint_as_float(u & 0xFFFF0000u); }

__device__ __forceinline__ void mma_bf16(float* c, const unsigned* a, const unsigned* b) {
    asm volatile(
        "mma.sync.aligned.m16n8k16.row.col.f32.bf16.bf16.f32 "
        "{%0,%1,%2,%3}, {%4,%5,%6,%7}, {%8,%9}, {%0,%1,%2,%3};\n"
        : "+f"(c[0]), "+f"(c[1]), "+f"(c[2]), "+f"(c[3])
        : "r"(a[0]), "r"(a[1]), "r"(a[2]), "r"(a[3]), "r"(b[0]), "r"(b[1]));
}
__device__ __forceinline__ void ldsm_x4(unsigned* r, uint32_t addr) {
    asm volatile("ldmatrix.sync.aligned.m8n8.x4.shared.b16 {%0,%1,%2,%3}, [%4];"
        : "=r"(r[0]), "=r"(r[1]), "=r"(r[2]), "=r"(r[3]) : "r"(addr));
}
__device__ __forceinline__ float blockReduceSum(float v) {
    #pragma unroll
    for (int o = 16; o; o >>= 1) v += __shfl_xor_sync(0xffffffffu, v, o);
    __shared__ float sm[16];
    int lane = threadIdx.x & 31, w = threadIdx.x >> 5;
    int nw = (blockDim.x + 31) >> 5;
    if (lane == 0) sm[w] = v;
    __syncthreads();
    if (w == 0) {
        v = (lane < nw) ? sm[lane] : 0.f;
        #pragma unroll
        for (int o = 8; o; o >>= 1) v += __shfl_xor_sync(0xffffffffu, v, o);
    }
    return v;  // valid on thread 0
}
__device__ __forceinline__ unsigned keyenc(float v) {
    unsigned u = __float_as_uint(v);
    return (u & 0x80000000u) ? ~u : (u | 0x80000000u);
}
__device__ __forceinline__ float keydec(unsigned u) {
    unsigned bits = (u & 0x80000000u) ? (u ^ 0x80000000u) : ~u;
    return __uint_as_float(bits);
}
__device__ __forceinline__ unsigned long long henc(float v) {
    long long q = __float2ll_rn(v * 1048576.f);
    return (1ULL << 44) + (unsigned long long)q;
}
__device__ __forceinline__ void hdec(unsigned long long p, int& cnt, double& sum) {
    long long s = ((long long)(p << 20)) >> 20;            // sign-extend low 44 bits
    cnt = (int)((p - (unsigned long long)s) >> 44);
    sum = (double)s * (1.0 / 1048576.0);
}

// ---------------- init ----------------
__global__ void k_init() {
    int i = blockIdx.x * blockDim.x + threadIdx.x;
    int stride = gridDim.x * blockDim.x;
    for (int x = i; x < N_*N_; x += stride) g_m2[x] = 0x7F800000u;
    for (int x = i; x < B_*N_; x += stride) g_m1[x] = 0x7F800000u;
    for (int x = i; x < B_*NBUCK; x += stride) { g_hP[x] = 0ull; g_hG[x] = 0ull; }
    if (i == 0) { g_mae = 0.0; g_s1 = 0.0; g_s2 = 0.0; }
}

// ---- fused MAE + bf16 conversion + norms + packed smem EMD histograms ----
#define FUSED_SMEM (2*NBUCK*8)   // 64 KB

__global__ void __launch_bounds__(256)
k_fused(const float* __restrict__ pred, const float* __restrict__ target) {
    extern __shared__ unsigned long long shl[];
    unsigned long long* hP = shl;           // [NBUCK]
    unsigned long long* hG = shl + NBUCK;   // [NBUCK]

    const int t = threadIdx.x;
    const int lane = t & 31, w = t >> 5;
    const int batch = blockIdx.x >> 3;
    const int chunk = blockIdx.x & 7;
    const int row0 = batch * N_ + chunk * 128;

    for (int i = t; i < NBUCK; i += 256) { hP[i] = 0ull; hG[i] = 0ull; }
    __syncthreads();

    uint2* bfP2 = reinterpret_cast<uint2*>(g_bfP);
    uint2* bfG2 = reinterpret_cast<uint2*>(g_bfG);

    float macc = 0.f;
    for (int pass = 0; pass < 16; ++pass) {
        int row = row0 + pass*8 + w;
        float4 p  = reinterpret_cast<const float4*>(pred)[row*32 + lane];
        float4 tg = reinterpret_cast<const float4*>(target)[row*32 + lane];
        macc += fabsf(p.x-tg.x)+fabsf(p.y-tg.y)+fabsf(p.z-tg.z)+fabsf(p.w-tg.w);
        // bf16 scratch
        uint2 up, ug;
        up.x = pack_bf16x2(p.x, p.y);
        up.y = pack_bf16x2(p.z, p.w);
        ug.x = pack_bf16x2(tg.x, tg.y);
        ug.y = pack_bf16x2(tg.z, tg.w);
        bfP2[row*32 + lane] = up;
        bfG2[row*32 + lane] = ug;
        // norms of bf16-rounded values (consistent with chamfer MMA inputs)
        {
            float a0 = bf_lo(up.x), a1 = bf_hi(up.x), a2 = bf_lo(up.y), a3 = bf_hi(up.y);
            float b0 = bf_lo(ug.x), b1 = bf_hi(ug.x), b2 = bf_lo(ug.y), b3 = bf_hi(ug.y);
            float np = a0*a0 + a1*a1 + a2*a2 + a3*a3;
            float nt = b0*b0 + b1*b1 + b2*b2 + b3*b3;
            #pragma unroll
            for (int o = 16; o; o >>= 1) {
                np += __shfl_xor_sync(0xffffffffu, np, o);
                nt += __shfl_xor_sync(0xffffffffu, nt, o);
            }
            if (lane == 0) { g_normP[row] = np; g_normT[row] = nt; }
        }
        // packed histograms (exact f32 values, fixed-point sums)
        atomicAdd(&hP[keyenc(p.x)  >> 20], henc(p.x));
        atomicAdd(&hP[keyenc(p.y)  >> 20], henc(p.y));
        atomicAdd(&hP[keyenc(p.z)  >> 20], henc(p.z));
        atomicAdd(&hP[keyenc(p.w)  >> 20], henc(p.w));
        atomicAdd(&hG[keyenc(tg.x) >> 20], henc(tg.x));
        atomicAdd(&hG[keyenc(tg.y) >> 20], henc(tg.y));
        atomicAdd(&hG[keyenc(tg.z) >> 20], henc(tg.z));
        atomicAdd(&hG[keyenc(tg.w) >> 20], henc(tg.w));
    }

    // MAE reduce
    #pragma unroll
    for (int o = 16; o; o >>= 1) macc += __shfl_xor_sync(0xffffffffu, macc, o);
    __shared__ float bsum;
    if (t == 0) bsum = 0.f;
    __syncthreads();
    if (lane == 0) atomicAdd(&bsum, macc);
    __syncthreads();
    if (t == 0) atomicAdd(&g_mae, (double)bsum);

    // merge populated buckets to global (single 64-bit atomic each)
    const size_t boff = (size_t)batch * NBUCK;
    for (int i = t; i < NBUCK; i += 256) {
        unsigned long long p = hP[i];
        if (p) atomicAdd(&g_hP[boff+i], p);
        p = hG[i];
        if (p) atomicAdd(&g_hG[boff+i], p);
    }
}

// ---------------- chamfer: bf16 MMA + ldmatrix (R10 version) ----------------
#define TI 128
#define TJ 128
#define BB 8
#define SROW 68   // u32 stride per row: 272B == 4 banks (mod 32) -> LDSM conflict-free
#define CHAM_SMEM ((2*128*SROW + 256) * 4)

__global__ void __launch_bounds__(512, 1)
k_chamfer() {
    extern __shared__ unsigned smem_u[];
    unsigned* As = smem_u;                     // [128][SROW] bf16x2
    unsigned* Bs = smem_u + 128*SROW;
    float* sNp = (float*)(smem_u + 2*128*SROW);  // [128]
    float* sNt = sNp + 128;

    const int tid  = threadIdx.x;
    const int lane = tid & 31;
    const int warp = tid >> 5;           // 0..15
    const int wi = warp >> 2;            // 0..3
    const int wj = warp & 3;             // 0..3
    const int g  = lane >> 2;            // 0..7
    const int cc = lane & 3;             // 0..3

    const int i0 = blockIdx.x * TI;
    const int j0 = blockIdx.y * TJ;
    const int b0 = blockIdx.z * BB;

    const uint2* bfP2 = reinterpret_cast<const uint2*>(g_bfP);
    const uint2* bfG2 = reinterpret_cast<const uint2*>(g_bfG);

    // per-lane ldmatrix byte addresses
    uint32_t smem_a = (uint32_t)__cvta_generic_to_shared(As);
    uint32_t smem_b = (uint32_t)__cvta_generic_to_shared(Bs);
    uint32_t aAddr[2], bAddr[2];
    #pragma unroll
    for (int mt = 0; mt < 2; ++mt) {
        int row = wi*32 + mt*16 + (lane & 15);
        aAddr[mt] = smem_a + (row*SROW + (lane >> 4)*4) * 4;
    }
    #pragma unroll
    for (int p = 0; p < 2; ++p) {
        int q = lane >> 3;                                  // 0..3
        int jr = wj*32 + (p*2 + (q >> 1))*8 + (lane & 7);   // two n8 tiles per LDSM
        bAddr[p] = smem_b + (jr*SROW + (q & 1)*4) * 4;
    }

    float dmin[2][4][4];
    #pragma unroll
    for (int mt = 0; mt < 2; mt++)
        #pragma unroll
        for (int nt = 0; nt < 4; nt++)
            #pragma unroll
            for (int q = 0; q < 4; q++) dmin[mt][nt][q] = 3.4e38f;

    for (int bi = 0; bi < BB; ++bi) {
        const int b = b0 + bi;
        __syncthreads();
        // load bf16 tiles (warp = one row per iter) + norms
        #pragma unroll
        for (int r = 0; r < 8; ++r) {
            int row = r*16 + warp;     // 0..127
            *reinterpret_cast<uint2*>(&As[row*SROW + lane*2]) = bfP2[((size_t)b*N_ + i0 + row)*32 + lane];
            *reinterpret_cast<uint2*>(&Bs[row*SROW + lane*2]) = bfG2[((size_t)b*N_ + j0 + row)*32 + lane];
        }
        if (tid < 128)       sNp[tid] = g_normP[b*N_ + i0 + tid];
        else if (tid < 256)  sNt[tid-128] = g_normT[b*N_ + j0 + (tid-128)];
        __syncthreads();

        float acc[2][4][4];
        #pragma unroll
        for (int mt = 0; mt < 2; mt++)
            #pragma unroll
            for (int nt = 0; nt < 4; nt++)
                #pragma unroll
                for (int q = 0; q < 4; q++) acc[mt][nt][q] = 0.f;

        #pragma unroll
        for (int ks = 0; ks < 8; ++ks) {
            unsigned a[2][4], bf[2][4];
            ldsm_x4(a[0],  aAddr[0] + ks*32);
            ldsm_x4(a[1],  aAddr[1] + ks*32);
            ldsm_x4(bf[0], bAddr[0] + ks*32);
            ldsm_x4(bf[1], bAddr[1] + ks*32);
            #pragma unroll
            for (int mt = 0; mt < 2; ++mt)
                #pragma unroll
                for (int nt = 0; nt < 4; ++nt) {
                    unsigned bb[2] = { bf[nt>>1][(nt&1)*2], bf[nt>>1][(nt&1)*2 + 1] };
                    mma_bf16(acc[mt][nt], a[mt], bb);
                }
        }

        float nP[2][2];
        #pragma unroll
        for (int mt = 0; mt < 2; ++mt) {
            int r0 = wi*32 + mt*16 + g;
            nP[mt][0] = sNp[r0];
            nP[mt][1] = sNp[r0+8];
        }
        #pragma unroll
        for (int nt = 0; nt < 4; ++nt) {
            int cA = wj*32 + nt*8 + 2*cc;
            float nt0 = sNt[cA], nt1 = sNt[cA+1];
            float cm0 = 3.4e38f, cm1 = 3.4e38f;
            #pragma unroll
            for (int mt = 0; mt < 2; ++mt) {
                float s0 = fmaxf(fmaf(-2.f, acc[mt][nt][0], nP[mt][0] + nt0), 1e-12f);
                float s1 = fmaxf(fmaf(-2.f, acc[mt][nt][1], nP[mt][0] + nt1), 1e-12f);
                float s2 = fmaxf(fmaf(-2.f, acc[mt][nt][2], nP[mt][1] + nt0), 1e-12f);
                float s3 = fmaxf(fmaf(-2.f, acc[mt][nt][3], nP[mt][1] + nt1), 1e-12f);
                dmin[mt][nt][0] = fminf(dmin[mt][nt][0], s0);
                dmin[mt][nt][1] = fminf(dmin[mt][nt][1], s1);
                dmin[mt][nt][2] = fminf(dmin[mt][nt][2], s2);
                dmin[mt][nt][3] = fminf(dmin[mt][nt][3], s3);
                cm0 = fminf(cm0, fminf(s0, s2));
                cm1 = fminf(cm1, fminf(s1, s3));
            }
            #pragma unroll
            for (int o = 4; o <= 16; o <<= 1) {
                cm0 = fminf(cm0, __shfl_xor_sync(0xffffffffu, cm0, o));
                cm1 = fminf(cm1, __shfl_xor_sync(0xffffffffu, cm1, o));
            }
            if (g == 0) {
                atomicMin(&g_m1[b*N_ + j0 + cA],     __float_as_uint(cm0));
                atomicMin(&g_m1[b*N_ + j0 + cA + 1], __float_as_uint(cm1));
            }
        }
    }

    #pragma unroll
    for (int mt = 0; mt < 2; ++mt) {
        int r0 = i0 + wi*32 + mt*16 + g;
        #pragma unroll
        for (int nt = 0; nt < 4; ++nt) {
            int cA = j0 + wj*32 + nt*8 + 2*cc;
            atomicMin(&g_m2[r0*N_ + cA],       __float_as_uint(dmin[mt][nt][0]));
            atomicMin(&g_m2[r0*N_ + cA + 1],   __float_as_uint(dmin[mt][nt][1]));
            atomicMin(&g_m2[(r0+8)*N_ + cA],   __float_as_uint(dmin[mt][nt][2]));
            atomicMin(&g_m2[(r0+8)*N_ + cA+1], __float_as_uint(dmin[mt][nt][3]));
        }
    }
}

// ---------------- merged chamfer reductions (vectorized, sqrt here) ----------------
__global__ void k_red() {
    int t = threadIdx.x;
    const uint4* m1v = reinterpret_cast<const uint4*>(g_m1);
    const uint4* m2v = reinterpret_cast<const uint4*>(g_m2);
    float s = 0.f;
    if (blockIdx.x < 16) {
        for (int i = blockIdx.x*256 + t; i < B_*N_/4; i += 16*256) {
            uint4 v = m1v[i];
            s += sqrtf(__uint_as_float(v.x)) + sqrtf(__uint_as_float(v.y))
               + sqrtf(__uint_as_float(v.z)) + sqrtf(__uint_as_float(v.w));
        }
        s = blockReduceSum(s);
        if (t == 0) atomicAdd(&g_s1, (double)s);
    } else {
        for (int i = (blockIdx.x-16)*256 + t; i < N_*N_/4; i += 240*256) {
            uint4 v = m2v[i];
            s += sqrtf(__uint_as_float(v.x)) + sqrtf(__uint_as_float(v.y))
               + sqrtf(__uint_as_float(v.z)) + sqrtf(__uint_as_float(v.w));
        }
        s = blockReduceSum(s);
        if (t == 0) atomicAdd(&g_s2, (double)s);
    }
}

// ---------------- EMD via CDF integral over buckets ----------------
__global__ void __launch_bounds__(1024) k_emdcdf() {
    const int b = blockIdx.x;
    const unsigned long long* __restrict__ hp = g_hP + (size_t)b * NBUCK;
    const unsigned long long* __restrict__ hg = g_hG + (size_t)b * NBUCK;
    const int t = threadIdx.x, lane = t & 31, w = t >> 5;
    __shared__ int wsum[32];
    __shared__ int carrysh;
    __shared__ double dsm[32];
    if (t == 0) carrysh = 0;
    __syncthreads();
    double acc = 0.0;
    for (int it = 0; it < NBUCK; it += 1024) {
        int idx = it + t;
        int cu; double su; hdec(hp[idx], cu, su);
        int cv; double sv; hdec(hg[idx], cv, sv);
        int d = cu - cv;
        int cold = carrysh;
        int x = d;
        #pragma unroll
        for (int o = 1; o < 32; o <<= 1) {
            int y = __shfl_up_sync(0xffffffffu, x, o);
            if (lane >= o) x += y;
        }
        if (lane == 31) wsum[w] = x;
        __syncthreads();
        if (w == 0) {
            int v = wsum[lane];
            #pragma unroll
            for (int o = 1; o < 32; o <<= 1) {
                int y = __shfl_up_sync(0xffffffffu, v, o);
                if (lane >= o) v += y;
            }
            wsum[lane] = v;
        }
        __syncthreads();
        int excl = cold + x - d + (w ? wsum[w-1] : 0);
        if (((cu | cv) != 0) || (excl != 0)) {
            unsigned kb = (unsigned)idx << 20;
            double L = (double)keydec(kb);
            double R = (double)keydec(kb + 0x100000u);
            double contrib = (double)excl * (R - L)
                           + (double)cu * R - su
                           - (double)cv * R + sv;
            acc += fabs(contrib);
        }
        __syncthreads();
        if (t == 0) carrysh = cold + wsum[31];
        __syncthreads();
    }
    #pragma unroll
    for (int o = 16; o; o >>= 1) acc += __shfl_xor_sync(0xffffffffu, acc, o);
    if (lane == 0) dsm[w] = acc;
    __syncthreads();
    if (w == 0) {
        acc = dsm[lane];
        #pragma unroll
        for (int o = 16; o; o >>= 1) acc += __shfl_xor_sync(0xffffffffu, acc, o);
        if (t == 0) g_emd[b] = acc;
    }
}

// ---------------- final combine ----------------
__global__ void k_final(float* out) {
    int b = threadIdx.x;
    if (b < B_) {
        double mae  = g_mae / (double)TOT;
        double cham = g_s1 / (double)(B_*N_) + g_s2 / (double)(N_*N_);
        out[b] = (float)(mae + cham + g_emd[b] / (double)NDF);
    }
}

extern "C" void kernel_launch(void* const* d_in, const int* in_sizes, int n_in,
                              void* d_out, int out_size) {
    const float* pred   = (const float*)d_in[0];
    const float* target = (const float*)d_in[1];
    float* out = (float*)d_out;

    cudaFuncSetAttribute(k_chamfer, cudaFuncAttributeMaxDynamicSharedMemorySize, CHAM_SMEM);
    cudaFuncSetAttribute(k_fused,   cudaFuncAttributeMaxDynamicSharedMemorySize, FUSED_SMEM);

    k_init<<<512, 256>>>();
    k_fused<<<256, 256, FUSED_SMEM>>>(pred, target);
    k_chamfer<<<dim3(8, 8, 4), 512, CHAM_SMEM>>>();
    k_red<<<256, 256>>>();
    k_emdcdf<<<B_, 1024>>>();
    k_final<<<1, 32>>>(out);
}

// round 13
// speedup vs baseline: 1.1598x; 1.1598x over previous
#include <cuda_runtime.h>
#include <cuda_bf16.h>
#include <cstdint>

#define B_  32
#define N_  1024
#define D_  128
#define NDF (N_*D_)          // 131072 per batch per tensor
#define TOT (B_*N_*D_)       // 4194304
#define NBUCK 4096           // 12-bit monotone-key prefix buckets

// ---------------- device scratch ----------------
__device__ float    g_normP[B_*N_];
__device__ float    g_normT[B_*N_];
__device__ unsigned g_m1[B_*N_];       // min_i d^2 (float bits)
__device__ unsigned g_m2[N_*N_];       // min_b d^2 (float bits)
__device__ double   g_mae, g_s1, g_s2;
__device__ double   g_emd[B_];
__device__ unsigned g_cntP[B_*NBUCK];
__device__ unsigned g_cntG[B_*NBUCK];
__device__ float    g_sumP[B_*NBUCK];
__device__ float    g_sumG[B_*NBUCK];
__device__ unsigned g_bfP[TOT/2];      // bf16x2 packed pred
__device__ unsigned g_bfG[TOT/2];      // bf16x2 packed target

// ---------------- helpers ----------------
__device__ __forceinline__ unsigned pack_bf16x2(float lo, float hi) {
    unsigned r;
    asm("cvt.rn.bf16x2.f32 %0, %1, %2;" : "=r"(r) : "f"(hi), "f"(lo));
    return r;
}
__device__ __forceinline__ float bf_lo(unsigned u) { return __uint_as_float(u << 16); }
__device__ __forceinline__ float bf_hi(unsigned u) { return __uint_as_float(u & 0xFFFF0000u); }

__device__ __forceinline__ void mma_bf16(float* c, const unsigned* a, const unsigned* b) {
    asm volatile(
        "mma.sync.aligned.m16n8k16.row.col.f32.bf16.bf16.f32 "
        "{%0,%1,%2,%3}, {%4,%5,%6,%7}, {%8,%9}, {%0,%1,%2,%3};\n"
        : "+f"(c[0]), "+f"(c[1]), "+f"(c[2]), "+f"(c[3])
        : "r"(a[0]), "r"(a[1]), "r"(a[2]), "r"(a[3]), "r"(b[0]), "r"(b[1]));
}
__device__ __forceinline__ void ldsm_x4(unsigned* r, uint32_t addr) {
    asm volatile("ldmatrix.sync.aligned.m8n8.x4.shared.b16 {%0,%1,%2,%3}, [%4];"
        : "=r"(r[0]), "=r"(r[1]), "=r"(r[2]), "=r"(r[3]) : "r"(addr));
}
__device__ __forceinline__ float blockReduceSum(float v) {
    #pragma unroll
    for (int o = 16; o; o >>= 1) v += __shfl_xor_sync(0xffffffffu, v, o);
    __shared__ float sm[32];
    int lane = threadIdx.x & 31, w = threadIdx.x >> 5;
    int nw = (blockDim.x + 31) >> 5;
    if (lane == 0) sm[w] = v;
    __syncthreads();
    if (w == 0) {
        v = (lane < nw) ? sm[lane] : 0.f;
        #pragma unroll
        for (int o = 16; o; o >>= 1) v += __shfl_xor_sync(0xffffffffu, v, o);
    }
    return v;  // valid on thread 0
}
__device__ __forceinline__ unsigned keyenc(float v) {
    unsigned u = __float_as_uint(v);
    return (u & 0x80000000u) ? ~u : (u | 0x80000000u);
}
__device__ __forceinline__ float keydec(unsigned u) {
    unsigned bits = (u & 0x80000000u) ? (u ^ 0x80000000u) : ~u;
    return __uint_as_float(bits);
}

// ---------------- init ----------------
__global__ void k_init() {
    int i = blockIdx.x * blockDim.x + threadIdx.x;
    int stride = gridDim.x * blockDim.x;
    for (int x = i; x < N_*N_; x += stride) g_m2[x] = 0x7F800000u;
    for (int x = i; x < B_*N_; x += stride) g_m1[x] = 0x7F800000u;
    for (int x = i; x < B_*NBUCK; x += stride) {
        g_cntP[x] = 0u; g_cntG[x] = 0u;
        g_sumP[x] = 0.f; g_sumG[x] = 0.f;
    }
    if (i == 0) { g_mae = 0.0; g_s1 = 0.0; g_s2 = 0.0; }
}

// ---- fused MAE + bf16 conversion + norms + smem-privatized EMD histograms ----
#define FUSED_SMEM (4*NBUCK*4)   // 64 KB

__global__ void __launch_bounds__(256)
k_fused(const float* __restrict__ pred, const float* __restrict__ target) {
    extern __shared__ unsigned sh[];
    unsigned* scP = sh;                 // [NBUCK]
    float*    ssP = (float*)(sh + NBUCK);
    unsigned* scG = sh + 2*NBUCK;
    float*    ssG = (float*)(sh + 3*NBUCK);

    const int t = threadIdx.x;
    const int lane = t & 31, w = t >> 5;
    const int batch = blockIdx.x >> 3;
    const int chunk = blockIdx.x & 7;
    const int row0 = batch * N_ + chunk * 128;

    for (int i = t; i < NBUCK; i += 256) {
        scP[i] = 0u; ssP[i] = 0.f; scG[i] = 0u; ssG[i] = 0.f;
    }
    __syncthreads();

    uint2* bfP2 = reinterpret_cast<uint2*>(g_bfP);
    uint2* bfG2 = reinterpret_cast<uint2*>(g_bfG);

    float macc = 0.f;
    for (int pass = 0; pass < 16; ++pass) {
        int row = row0 + pass*8 + w;
        float4 p  = reinterpret_cast<const float4*>(pred)[row*32 + lane];
        float4 tg = reinterpret_cast<const float4*>(target)[row*32 + lane];
        macc += fabsf(p.x-tg.x)+fabsf(p.y-tg.y)+fabsf(p.z-tg.z)+fabsf(p.w-tg.w);
        // bf16 scratch
        uint2 up, ug;
        up.x = pack_bf16x2(p.x, p.y);
        up.y = pack_bf16x2(p.z, p.w);
        ug.x = pack_bf16x2(tg.x, tg.y);
        ug.y = pack_bf16x2(tg.z, tg.w);
        bfP2[row*32 + lane] = up;
        bfG2[row*32 + lane] = ug;
        // norms of bf16-rounded values (consistent with chamfer MMA inputs)
        {
            float a0 = bf_lo(up.x), a1 = bf_hi(up.x), a2 = bf_lo(up.y), a3 = bf_hi(up.y);
            float b0 = bf_lo(ug.x), b1 = bf_hi(ug.x), b2 = bf_lo(ug.y), b3 = bf_hi(ug.y);
            float np = a0*a0 + a1*a1 + a2*a2 + a3*a3;
            float nt = b0*b0 + b1*b1 + b2*b2 + b3*b3;
            #pragma unroll
            for (int o = 16; o; o >>= 1) {
                np += __shfl_xor_sync(0xffffffffu, np, o);
                nt += __shfl_xor_sync(0xffffffffu, nt, o);
            }
            if (lane == 0) { g_normP[row] = np; g_normT[row] = nt; }
        }
        // histograms (exact f32 values)
        atomicAdd(&scP[keyenc(p.x)  >> 20], 1u); atomicAdd(&ssP[keyenc(p.x)  >> 20], p.x);
        atomicAdd(&scP[keyenc(p.y)  >> 20], 1u); atomicAdd(&ssP[keyenc(p.y)  >> 20], p.y);
        atomicAdd(&scP[keyenc(p.z)  >> 20], 1u); atomicAdd(&ssP[keyenc(p.z)  >> 20], p.z);
        atomicAdd(&scP[keyenc(p.w)  >> 20], 1u); atomicAdd(&ssP[keyenc(p.w)  >> 20], p.w);
        atomicAdd(&scG[keyenc(tg.x) >> 20], 1u); atomicAdd(&ssG[keyenc(tg.x) >> 20], tg.x);
        atomicAdd(&scG[keyenc(tg.y) >> 20], 1u); atomicAdd(&ssG[keyenc(tg.y) >> 20], tg.y);
        atomicAdd(&scG[keyenc(tg.z) >> 20], 1u); atomicAdd(&ssG[keyenc(tg.z) >> 20], tg.z);
        atomicAdd(&scG[keyenc(tg.w) >> 20], 1u); atomicAdd(&ssG[keyenc(tg.w) >> 20], tg.w);
    }

    // MAE reduce
    #pragma unroll
    for (int o = 16; o; o >>= 1) macc += __shfl_xor_sync(0xffffffffu, macc, o);
    __shared__ float bsum;
    if (t == 0) bsum = 0.f;
    __syncthreads();
    if (lane == 0) atomicAdd(&bsum, macc);
    __syncthreads();
    if (t == 0) atomicAdd(&g_mae, (double)bsum);

    // merge populated buckets to global
    const size_t boff = (size_t)batch * NBUCK;
    for (int i = t; i < NBUCK; i += 256) {
        unsigned c = scP[i];
        if (c) { atomicAdd(&g_cntP[boff+i], c); atomicAdd(&g_sumP[boff+i], ssP[i]); }
        c = scG[i];
        if (c) { atomicAdd(&g_cntG[boff+i], c); atomicAdd(&g_sumG[boff+i], ssG[i]); }
    }
}

// ---- chamfer: bf16 MMA + ldmatrix, single wave (128 blocks, BB=16) ----
#define TI 128
#define TJ 128
#define BB 16
#define SROW 68   // u32 stride per row: 272B == 4 banks (mod 32) -> LDSM conflict-free
#define CHAM_SMEM ((2*128*SROW + 256) * 4)

__global__ void __launch_bounds__(512, 1)
k_chamfer() {
    extern __shared__ unsigned smem_u[];
    unsigned* As = smem_u;                     // [128][SROW] bf16x2
    unsigned* Bs = smem_u + 128*SROW;
    float* sNp = (float*)(smem_u + 2*128*SROW);  // [128]
    float* sNt = sNp + 128;

    const int tid  = threadIdx.x;
    const int lane = tid & 31;
    const int warp = tid >> 5;           // 0..15
    const int wi = warp >> 2;            // 0..3
    const int wj = warp & 3;             // 0..3
    const int g  = lane >> 2;            // 0..7
    const int cc = lane & 3;             // 0..3

    const int i0 = blockIdx.x * TI;
    const int j0 = blockIdx.y * TJ;
    const int b0 = blockIdx.z * BB;

    const uint2* bfP2 = reinterpret_cast<const uint2*>(g_bfP);
    const uint2* bfG2 = reinterpret_cast<const uint2*>(g_bfG);

    // per-lane ldmatrix byte addresses
    uint32_t smem_a = (uint32_t)__cvta_generic_to_shared(As);
    uint32_t smem_b = (uint32_t)__cvta_generic_to_shared(Bs);
    uint32_t aAddr[2], bAddr[2];
    #pragma unroll
    for (int mt = 0; mt < 2; ++mt) {
        int row = wi*32 + mt*16 + (lane & 15);
        aAddr[mt] = smem_a + (row*SROW + (lane >> 4)*4) * 4;
    }
    #pragma unroll
    for (int p = 0; p < 2; ++p) {
        int q = lane >> 3;                                  // 0..3
        int jr = wj*32 + (p*2 + (q >> 1))*8 + (lane & 7);   // two n8 tiles per LDSM
        bAddr[p] = smem_b + (jr*SROW + (q & 1)*4) * 4;
    }

    float dmin[2][4][4];
    #pragma unroll
    for (int mt = 0; mt < 2; mt++)
        #pragma unroll
        for (int nt = 0; nt < 4; nt++)
            #pragma unroll
            for (int q = 0; q < 4; q++) dmin[mt][nt][q] = 3.4e38f;

    for (int bi = 0; bi < BB; ++bi) {
        const int b = b0 + bi;
        __syncthreads();
        // load bf16 tiles (warp = one row per iter) + norms
        #pragma unroll
        for (int r = 0; r < 8; ++r) {
            int row = r*16 + warp;     // 0..127
            *reinterpret_cast<uint2*>(&As[row*SROW + lane*2]) = bfP2[((size_t)b*N_ + i0 + row)*32 + lane];
            *reinterpret_cast<uint2*>(&Bs[row*SROW + lane*2]) = bfG2[((size_t)b*N_ + j0 + row)*32 + lane];
        }
        if (tid < 128)       sNp[tid] = g_normP[b*N_ + i0 + tid];
        else if (tid < 256)  sNt[tid-128] = g_normT[b*N_ + j0 + (tid-128)];
        __syncthreads();

        float acc[2][4][4];
        #pragma unroll
        for (int mt = 0; mt < 2; mt++)
            #pragma unroll
            for (int nt = 0; nt < 4; nt++)
                #pragma unroll
                for (int q = 0; q < 4; q++) acc[mt][nt][q] = 0.f;

        #pragma unroll
        for (int ks = 0; ks < 8; ++ks) {
            unsigned a[2][4], bf[2][4];
            ldsm_x4(a[0],  aAddr[0] + ks*32);
            ldsm_x4(a[1],  aAddr[1] + ks*32);
            ldsm_x4(bf[0], bAddr[0] + ks*32);
            ldsm_x4(bf[1], bAddr[1] + ks*32);
            #pragma unroll
            for (int mt = 0; mt < 2; ++mt)
                #pragma unroll
                for (int nt = 0; nt < 4; ++nt) {
                    unsigned bb[2] = { bf[nt>>1][(nt&1)*2], bf[nt>>1][(nt&1)*2 + 1] };
                    mma_bf16(acc[mt][nt], a[mt], bb);
                }
        }

        float nP[2][2];
        #pragma unroll
        for (int mt = 0; mt < 2; ++mt) {
            int r0 = wi*32 + mt*16 + g;
            nP[mt][0] = sNp[r0];
            nP[mt][1] = sNp[r0+8];
        }
        #pragma unroll
        for (int nt = 0; nt < 4; ++nt) {
            int cA = wj*32 + nt*8 + 2*cc;
            float nt0 = sNt[cA], nt1 = sNt[cA+1];
            float cm0 = 3.4e38f, cm1 = 3.4e38f;
            #pragma unroll
            for (int mt = 0; mt < 2; ++mt) {
                float s0 = fmaxf(fmaf(-2.f, acc[mt][nt][0], nP[mt][0] + nt0), 1e-12f);
                float s1 = fmaxf(fmaf(-2.f, acc[mt][nt][1], nP[mt][0] + nt1), 1e-12f);
                float s2 = fmaxf(fmaf(-2.f, acc[mt][nt][2], nP[mt][1] + nt0), 1e-12f);
                float s3 = fmaxf(fmaf(-2.f, acc[mt][nt][3], nP[mt][1] + nt1), 1e-12f);
                dmin[mt][nt][0] = fminf(dmin[mt][nt][0], s0);
                dmin[mt][nt][1] = fminf(dmin[mt][nt][1], s1);
                dmin[mt][nt][2] = fminf(dmin[mt][nt][2], s2);
                dmin[mt][nt][3] = fminf(dmin[mt][nt][3], s3);
                cm0 = fminf(cm0, fminf(s0, s2));
                cm1 = fminf(cm1, fminf(s1, s3));
            }
            #pragma unroll
            for (int o = 4; o <= 16; o <<= 1) {
                cm0 = fminf(cm0, __shfl_xor_sync(0xffffffffu, cm0, o));
                cm1 = fminf(cm1, __shfl_xor_sync(0xffffffffu, cm1, o));
            }
            if (g == 0) {
                atomicMin(&g_m1[b*N_ + j0 + cA],     __float_as_uint(cm0));
                atomicMin(&g_m1[b*N_ + j0 + cA + 1], __float_as_uint(cm1));
            }
        }
    }

    #pragma unroll
    for (int mt = 0; mt < 2; ++mt) {
        int r0 = i0 + wi*32 + mt*16 + g;
        #pragma unroll
        for (int nt = 0; nt < 4; ++nt) {
            int cA = j0 + wj*32 + nt*8 + 2*cc;
            atomicMin(&g_m2[r0*N_ + cA],       __float_as_uint(dmin[mt][nt][0]));
            atomicMin(&g_m2[r0*N_ + cA + 1],   __float_as_uint(dmin[mt][nt][1]));
            atomicMin(&g_m2[(r0+8)*N_ + cA],   __float_as_uint(dmin[mt][nt][2]));
            atomicMin(&g_m2[(r0+8)*N_ + cA+1], __float_as_uint(dmin[mt][nt][3]));
        }
    }
}

// ---- merged post pass: sqrt reductions (blocks 0..255) + EMD CDF (256..287) ----
__global__ void __launch_bounds__(1024) k_post() {
    const int bx = blockIdx.x;
    const int t = threadIdx.x, lane = t & 31, w = t >> 5;
    if (bx < 8) {
        const uint4* m1v = reinterpret_cast<const uint4*>(g_m1);
        float s = 0.f;
        for (int i = bx*1024 + t; i < B_*N_/4; i += 8*1024) {
            uint4 v = m1v[i];
            s += sqrtf(__uint_as_float(v.x)) + sqrtf(__uint_as_float(v.y))
               + sqrtf(__uint_as_float(v.z)) + sqrtf(__uint_as_float(v.w));
        }
        s = blockReduceSum(s);
        if (t == 0) atomicAdd(&g_s1, (double)s);
    } else if (bx < 256) {
        const uint4* m2v = reinterpret_cast<const uint4*>(g_m2);
        float s = 0.f;
        for (int i = (bx-8)*1024 + t; i < N_*N_/4; i += 248*1024) {
            uint4 v = m2v[i];
            s += sqrtf(__uint_as_float(v.x)) + sqrtf(__uint_as_float(v.y))
               + sqrtf(__uint_as_float(v.z)) + sqrtf(__uint_as_float(v.w));
        }
        s = blockReduceSum(s);
        if (t == 0) atomicAdd(&g_s2, (double)s);
    } else {
        const int b = bx - 256;
        const unsigned* __restrict__ cp = g_cntP + (size_t)b * NBUCK;
        const unsigned* __restrict__ cg = g_cntG + (size_t)b * NBUCK;
        const float*    __restrict__ sp = g_sumP + (size_t)b * NBUCK;
        const float*    __restrict__ sg = g_sumG + (size_t)b * NBUCK;
        __shared__ int wsum[32];
        __shared__ int carrysh;
        __shared__ double dsm[32];
        if (t == 0) carrysh = 0;
        __syncthreads();
        double acc = 0.0;
        for (int it = 0; it < NBUCK; it += 1024) {
            int idx = it + t;
            int cu = (int)cp[idx], cv = (int)cg[idx];
            int d = cu - cv;
            int cold = carrysh;
            int x = d;
            #pragma unroll
            for (int o = 1; o < 32; o <<= 1) {
                int y = __shfl_up_sync(0xffffffffu, x, o);
                if (lane >= o) x += y;
            }
            if (lane == 31) wsum[w] = x;
            __syncthreads();
            if (w == 0) {
                int v = wsum[lane];
                #pragma unroll
                for (int o = 1; o < 32; o <<= 1) {
                    int y = __shfl_up_sync(0xffffffffu, v, o);
                    if (lane >= o) v += y;
                }
                wsum[lane] = v;
            }
            __syncthreads();
            int excl = cold + x - d + (w ? wsum[w-1] : 0);
            if (((cu | cv) != 0) || (excl != 0)) {
                unsigned kb = (unsigned)idx << 20;
                double L = (double)keydec(kb);
                double R = (double)keydec(kb + 0x100000u);
                double contrib = (double)excl * (R - L)
                               + (double)cu * R - (double)sp[idx]
                               - (double)cv * R + (double)sg[idx];
                acc += fabs(contrib);
            }
            __syncthreads();
            if (t == 0) carrysh = cold + wsum[31];
            __syncthreads();
        }
        #pragma unroll
        for (int o = 16; o; o >>= 1) acc += __shfl_xor_sync(0xffffffffu, acc, o);
        if (lane == 0) dsm[w] = acc;
        __syncthreads();
        if (w == 0) {
            acc = dsm[lane];
            #pragma unroll
            for (int o = 16; o; o >>= 1) acc += __shfl_xor_sync(0xffffffffu, acc, o);
            if (t == 0) g_emd[b] = acc;
        }
    }
}

// ---------------- final combine ----------------
__global__ void k_final(float* out) {
    int b = threadIdx.x;
    if (b < B_) {
        double mae  = g_mae / (double)TOT;
        double cham = g_s1 / (double)(B_*N_) + g_s2 / (double)(N_*N_);
        out[b] = (float)(mae + cham + g_emd[b] / (double)NDF);
    }
}

extern "C" void kernel_launch(void* const* d_in, const int* in_sizes, int n_in,
                              void* d_out, int out_size) {
    const float* pred   = (const float*)d_in[0];
    const float* target = (const float*)d_in[1];
    float* out = (float*)d_out;

    cudaFuncSetAttribute(k_chamfer, cudaFuncAttributeMaxDynamicSharedMemorySize, CHAM_SMEM);
    cudaFuncSetAttribute(k_fused,   cudaFuncAttributeMaxDynamicSharedMemorySize, FUSED_SMEM);

    k_init<<<512, 256>>>();
    k_fused<<<256, 256, FUSED_SMEM>>>(pred, target);
    k_chamfer<<<dim3(8, 8, 2), 512, CHAM_SMEM>>>();
    k_post<<<288, 1024>>>();
    k_final<<<1, 32>>>(out);
}

// round 14
// speedup vs baseline: 1.1856x; 1.0223x over previous
#include <cuda_runtime.h>
#include <cuda_bf16.h>
#include <cstdint>

#define B_  32
#define N_  1024
#define D_  128
#define NDF (N_*D_)          // 131072 per batch per tensor
#define TOT (B_*N_*D_)       // 4194304
#define NBUCK 4096           // 12-bit monotone-key prefix buckets

// ---------------- device scratch (zero-init == ready state; all self-cleaning) ----------------
__device__ float    g_normP[B_*N_];
__device__ float    g_normT[B_*N_];
__device__ unsigned g_m1[B_*N_];       // max of (0x7F800000 - bits(d^2)); 0 == +inf
__device__ unsigned g_m2[N_*N_];
__device__ double   g_mae, g_s1, g_s2;
__device__ double   g_emd[B_];
__device__ unsigned g_cntP[B_*NBUCK];
__device__ unsigned g_cntG[B_*NBUCK];
__device__ float    g_sumP[B_*NBUCK];
__device__ float    g_sumG[B_*NBUCK];
__device__ unsigned g_bfP[TOT/2];      // bf16x2 packed pred
__device__ unsigned g_bfG[TOT/2];      // bf16x2 packed target

// ---------------- helpers ----------------
__device__ __forceinline__ unsigned pack_bf16x2(float lo, float hi) {
    unsigned r;
    asm("cvt.rn.bf16x2.f32 %0, %1, %2;" : "=r"(r) : "f"(hi), "f"(lo));
    return r;
}
__device__ __forceinline__ float bf_lo(unsigned u) { return __uint_as_float(u << 16); }
__device__ __forceinline__ float bf_hi(unsigned u) { return __uint_as_float(u & 0xFFFF0000u); }

__device__ __forceinline__ void mma_bf16(float* c, const unsigned* a, const unsigned* b) {
    asm volatile(
        "mma.sync.aligned.m16n8k16.row.col.f32.bf16.bf16.f32 "
        "{%0,%1,%2,%3}, {%4,%5,%6,%7}, {%8,%9}, {%0,%1,%2,%3};\n"
        : "+f"(c[0]), "+f"(c[1]), "+f"(c[2]), "+f"(c[3])
        : "r"(a[0]), "r"(a[1]), "r"(a[2]), "r"(a[3]), "r"(b[0]), "r"(b[1]));
}
__device__ __forceinline__ void ldsm_x4(unsigned* r, uint32_t addr) {
    asm volatile("ldmatrix.sync.aligned.m8n8.x4.shared.b16 {%0,%1,%2,%3}, [%4];"
        : "=r"(r[0]), "=r"(r[1]), "=r"(r[2]), "=r"(r[3]) : "r"(addr));
}
__device__ __forceinline__ float blockReduceSum(float v) {
    #pragma unroll
    for (int o = 16; o; o >>= 1) v += __shfl_xor_sync(0xffffffffu, v, o);
    __shared__ float sm[32];
    int lane = threadIdx.x & 31, w = threadIdx.x >> 5;
    int nw = (blockDim.x + 31) >> 5;
    if (lane == 0) sm[w] = v;
    __syncthreads();
    if (w == 0) {
        v = (lane < nw) ? sm[lane] : 0.f;
        #pragma unroll
        for (int o = 16; o; o >>= 1) v += __shfl_xor_sync(0xffffffffu, v, o);
    }
    return v;  // valid on thread 0
}
__device__ __forceinline__ unsigned keyenc(float v) {
    unsigned u = __float_as_uint(v);
    return (u & 0x80000000u) ? ~u : (u | 0x80000000u);
}
__device__ __forceinline__ float keydec(unsigned u) {
    unsigned bits = (u & 0x80000000u) ? (u ^ 0x80000000u) : ~u;
    return __uint_as_float(bits);
}
// negated-min encoding: larger == smaller d^2; 0 == +inf (matches static zero-init)
__device__ __forceinline__ unsigned minenc(float d2) {
    return 0x7F800000u - __float_as_uint(d2);
}
__device__ __forceinline__ float mindec(unsigned t) {
    return __uint_as_float(0x7F800000u - t);
}

// ---- fused MAE + bf16 conversion + norms + smem-privatized EMD histograms ----
#define FUSED_SMEM (4*NBUCK*4)   // 64 KB

__global__ void __launch_bounds__(256)
k_fused(const float* __restrict__ pred, const float* __restrict__ target) {
    extern __shared__ unsigned sh[];
    unsigned* scP = sh;                 // [NBUCK]
    float*    ssP = (float*)(sh + NBUCK);
    unsigned* scG = sh + 2*NBUCK;
    float*    ssG = (float*)(sh + 3*NBUCK);

    const int t = threadIdx.x;
    const int lane = t & 31, w = t >> 5;
    const int batch = blockIdx.x >> 3;
    const int chunk = blockIdx.x & 7;
    const int row0 = batch * N_ + chunk * 128;

    for (int i = t; i < NBUCK; i += 256) {
        scP[i] = 0u; ssP[i] = 0.f; scG[i] = 0u; ssG[i] = 0.f;
    }
    __syncthreads();

    uint2* bfP2 = reinterpret_cast<uint2*>(g_bfP);
    uint2* bfG2 = reinterpret_cast<uint2*>(g_bfG);

    float macc = 0.f;
    for (int pass = 0; pass < 16; ++pass) {
        int row = row0 + pass*8 + w;
        float4 p  = reinterpret_cast<const float4*>(pred)[row*32 + lane];
        float4 tg = reinterpret_cast<const float4*>(target)[row*32 + lane];
        macc += fabsf(p.x-tg.x)+fabsf(p.y-tg.y)+fabsf(p.z-tg.z)+fabsf(p.w-tg.w);
        // bf16 scratch
        uint2 up, ug;
        up.x = pack_bf16x2(p.x, p.y);
        up.y = pack_bf16x2(p.z, p.w);
        ug.x = pack_bf16x2(tg.x, tg.y);
        ug.y = pack_bf16x2(tg.z, tg.w);
        bfP2[row*32 + lane] = up;
        bfG2[row*32 + lane] = ug;
        // norms of bf16-rounded values (consistent with chamfer MMA inputs)
        {
            float a0 = bf_lo(up.x), a1 = bf_hi(up.x), a2 = bf_lo(up.y), a3 = bf_hi(up.y);
            float b0 = bf_lo(ug.x), b1 = bf_hi(ug.x), b2 = bf_lo(ug.y), b3 = bf_hi(ug.y);
            float np = a0*a0 + a1*a1 + a2*a2 + a3*a3;
            float nt = b0*b0 + b1*b1 + b2*b2 + b3*b3;
            #pragma unroll
            for (int o = 16; o; o >>= 1) {
                np += __shfl_xor_sync(0xffffffffu, np, o);
                nt += __shfl_xor_sync(0xffffffffu, nt, o);
            }
            if (lane == 0) { g_normP[row] = np; g_normT[row] = nt; }
        }
        // histograms (exact f32 values)
        atomicAdd(&scP[keyenc(p.x)  >> 20], 1u); atomicAdd(&ssP[keyenc(p.x)  >> 20], p.x);
        atomicAdd(&scP[keyenc(p.y)  >> 20], 1u); atomicAdd(&ssP[keyenc(p.y)  >> 20], p.y);
        atomicAdd(&scP[keyenc(p.z)  >> 20], 1u); atomicAdd(&ssP[keyenc(p.z)  >> 20], p.z);
        atomicAdd(&scP[keyenc(p.w)  >> 20], 1u); atomicAdd(&ssP[keyenc(p.w)  >> 20], p.w);
        atomicAdd(&scG[keyenc(tg.x) >> 20], 1u); atomicAdd(&ssG[keyenc(tg.x) >> 20], tg.x);
        atomicAdd(&scG[keyenc(tg.y) >> 20], 1u); atomicAdd(&ssG[keyenc(tg.y) >> 20], tg.y);
        atomicAdd(&scG[keyenc(tg.z) >> 20], 1u); atomicAdd(&ssG[keyenc(tg.z) >> 20], tg.z);
        atomicAdd(&scG[keyenc(tg.w) >> 20], 1u); atomicAdd(&ssG[keyenc(tg.w) >> 20], tg.w);
    }

    // MAE reduce
    #pragma unroll
    for (int o = 16; o; o >>= 1) macc += __shfl_xor_sync(0xffffffffu, macc, o);
    __shared__ float bsum;
    if (t == 0) bsum = 0.f;
    __syncthreads();
    if (lane == 0) atomicAdd(&bsum, macc);
    __syncthreads();
    if (t == 0) atomicAdd(&g_mae, (double)bsum);

    // merge populated buckets to global
    const size_t boff = (size_t)batch * NBUCK;
    for (int i = t; i < NBUCK; i += 256) {
        unsigned c = scP[i];
        if (c) { atomicAdd(&g_cntP[boff+i], c); atomicAdd(&g_sumP[boff+i], ssP[i]); }
        c = scG[i];
        if (c) { atomicAdd(&g_cntG[boff+i], c); atomicAdd(&g_sumG[boff+i], ssG[i]); }
    }
}

// ---- chamfer: bf16 MMA + ldmatrix, single wave (128 blocks, BB=16) ----
#define TI 128
#define TJ 128
#define BB 16
#define SROW 68   // u32 stride per row: 272B == 4 banks (mod 32) -> LDSM conflict-free
#define CHAM_SMEM ((2*128*SROW + 256) * 4)

__global__ void __launch_bounds__(512, 1)
k_chamfer() {
    extern __shared__ unsigned smem_u[];
    unsigned* As = smem_u;                     // [128][SROW] bf16x2
    unsigned* Bs = smem_u + 128*SROW;
    float* sNp = (float*)(smem_u + 2*128*SROW);  // [128]
    float* sNt = sNp + 128;

    const int tid  = threadIdx.x;
    const int lane = tid & 31;
    const int warp = tid >> 5;           // 0..15
    const int wi = warp >> 2;            // 0..3
    const int wj = warp & 3;             // 0..3
    const int g  = lane >> 2;            // 0..7
    const int cc = lane & 3;             // 0..3

    const int i0 = blockIdx.x * TI;
    const int j0 = blockIdx.y * TJ;
    const int b0 = blockIdx.z * BB;

    const uint2* bfP2 = reinterpret_cast<const uint2*>(g_bfP);
    const uint2* bfG2 = reinterpret_cast<const uint2*>(g_bfG);

    // per-lane ldmatrix byte addresses
    uint32_t smem_a = (uint32_t)__cvta_generic_to_shared(As);
    uint32_t smem_b = (uint32_t)__cvta_generic_to_shared(Bs);
    uint32_t aAddr[2], bAddr[2];
    #pragma unroll
    for (int mt = 0; mt < 2; ++mt) {
        int row = wi*32 + mt*16 + (lane & 15);
        aAddr[mt] = smem_a + (row*SROW + (lane >> 4)*4) * 4;
    }
    #pragma unroll
    for (int p = 0; p < 2; ++p) {
        int q = lane >> 3;                                  // 0..3
        int jr = wj*32 + (p*2 + (q >> 1))*8 + (lane & 7);   // two n8 tiles per LDSM
        bAddr[p] = smem_b + (jr*SROW + (q & 1)*4) * 4;
    }

    float dmin[2][4][4];
    #pragma unroll
    for (int mt = 0; mt < 2; mt++)
        #pragma unroll
        for (int nt = 0; nt < 4; nt++)
            #pragma unroll
            for (int q = 0; q < 4; q++) dmin[mt][nt][q] = 3.4e38f;

    for (int bi = 0; bi < BB; ++bi) {
        const int b = b0 + bi;
        __syncthreads();
        // load bf16 tiles (warp = one row per iter) + norms
        #pragma unroll
        for (int r = 0; r < 8; ++r) {
            int row = r*16 + warp;     // 0..127
            *reinterpret_cast<uint2*>(&As[row*SROW + lane*2]) = bfP2[((size_t)b*N_ + i0 + row)*32 + lane];
            *reinterpret_cast<uint2*>(&Bs[row*SROW + lane*2]) = bfG2[((size_t)b*N_ + j0 + row)*32 + lane];
        }
        if (tid < 128)       sNp[tid] = g_normP[b*N_ + i0 + tid];
        else if (tid < 256)  sNt[tid-128] = g_normT[b*N_ + j0 + (tid-128)];
        __syncthreads();

        float acc[2][4][4];
        #pragma unroll
        for (int mt = 0; mt < 2; mt++)
            #pragma unroll
            for (int nt = 0; nt < 4; nt++)
                #pragma unroll
                for (int q = 0; q < 4; q++) acc[mt][nt][q] = 0.f;

        #pragma unroll
        for (int ks = 0; ks < 8; ++ks) {
            unsigned a[2][4], bf[2][4];
            ldsm_x4(a[0],  aAddr[0] + ks*32);
            ldsm_x4(a[1],  aAddr[1] + ks*32);
            ldsm_x4(bf[0], bAddr[0] + ks*32);
            ldsm_x4(bf[1], bAddr[1] + ks*32);
            #pragma unroll
            for (int mt = 0; mt < 2; ++mt)
                #pragma unroll
                for (int nt = 0; nt < 4; ++nt) {
                    unsigned bb[2] = { bf[nt>>1][(nt&1)*2], bf[nt>>1][(nt&1)*2 + 1] };
                    mma_bf16(acc[mt][nt], a[mt], bb);
                }
        }

        float nP[2][2];
        #pragma unroll
        for (int mt = 0; mt < 2; ++mt) {
            int r0 = wi*32 + mt*16 + g;
            nP[mt][0] = sNp[r0];
            nP[mt][1] = sNp[r0+8];
        }
        #pragma unroll
        for (int nt = 0; nt < 4; ++nt) {
            int cA = wj*32 + nt*8 + 2*cc;
            float nt0 = sNt[cA], nt1 = sNt[cA+1];
            float cm0 = 3.4e38f, cm1 = 3.4e38f;
            #pragma unroll
            for (int mt = 0; mt < 2; ++mt) {
                float s0 = fmaxf(fmaf(-2.f, acc[mt][nt][0], nP[mt][0] + nt0), 1e-12f);
                float s1 = fmaxf(fmaf(-2.f, acc[mt][nt][1], nP[mt][0] + nt1), 1e-12f);
                float s2 = fmaxf(fmaf(-2.f, acc[mt][nt][2], nP[mt][1] + nt0), 1e-12f);
                float s3 = fmaxf(fmaf(-2.f, acc[mt][nt][3], nP[mt][1] + nt1), 1e-12f);
                dmin[mt][nt][0] = fminf(dmin[mt][nt][0], s0);
                dmin[mt][nt][1] = fminf(dmin[mt][nt][1], s1);
                dmin[mt][nt][2] = fminf(dmin[mt][nt][2], s2);
                dmin[mt][nt][3] = fminf(dmin[mt][nt][3], s3);
                cm0 = fminf(cm0, fminf(s0, s2));
                cm1 = fminf(cm1, fminf(s1, s3));
            }
            #pragma unroll
            for (int o = 4; o <= 16; o <<= 1) {
                cm0 = fminf(cm0, __shfl_xor_sync(0xffffffffu, cm0, o));
                cm1 = fminf(cm1, __shfl_xor_sync(0xffffffffu, cm1, o));
            }
            if (g == 0) {
                atomicMax(&g_m1[b*N_ + j0 + cA],     minenc(cm0));
                atomicMax(&g_m1[b*N_ + j0 + cA + 1], minenc(cm1));
            }
        }
    }

    #pragma unroll
    for (int mt = 0; mt < 2; ++mt) {
        int r0 = i0 + wi*32 + mt*16 + g;
        #pragma unroll
        for (int nt = 0; nt < 4; ++nt) {
            int cA = j0 + wj*32 + nt*8 + 2*cc;
            atomicMax(&g_m2[r0*N_ + cA],       minenc(dmin[mt][nt][0]));
            atomicMax(&g_m2[r0*N_ + cA + 1],   minenc(dmin[mt][nt][1]));
            atomicMax(&g_m2[(r0+8)*N_ + cA],   minenc(dmin[mt][nt][2]));
            atomicMax(&g_m2[(r0+8)*N_ + cA+1], minenc(dmin[mt][nt][3]));
        }
    }
}

// ---- post pass: EMD CDF (blocks 0..31), m1 sqrt-sum (32..39), m2 sqrt-sum (40..287) ----
// Self-cleaning: every scratch word read here is re-zeroed for the next call.
__global__ void __launch_bounds__(1024) k_post() {
    const int bx = blockIdx.x;
    const int t = threadIdx.x, lane = t & 31, w = t >> 5;
    if (bx < 32) {
        // single-pass CDF: thread t owns buckets 4t..4t+3
        const int b = bx;
        unsigned* cp = g_cntP + (size_t)b * NBUCK;
        unsigned* cg = g_cntG + (size_t)b * NBUCK;
        float*    sp = g_sumP + (size_t)b * NBUCK;
        float*    sg = g_sumG + (size_t)b * NBUCK;
        uint4 cu4 = reinterpret_cast<uint4*>(cp)[t];
        uint4 cv4 = reinterpret_cast<uint4*>(cg)[t];
        float4 su4 = reinterpret_cast<float4*>(sp)[t];
        float4 sv4 = reinterpret_cast<float4*>(sg)[t];
        int cu[4] = {(int)cu4.x,(int)cu4.y,(int)cu4.z,(int)cu4.w};
        int cv[4] = {(int)cv4.x,(int)cv4.y,(int)cv4.z,(int)cv4.w};
        float su[4] = {su4.x,su4.y,su4.z,su4.w};
        float sv[4] = {sv4.x,sv4.y,sv4.z,sv4.w};
        int pre[4]; int tot = 0;
        #pragma unroll
        for (int j = 0; j < 4; ++j) { pre[j] = tot; tot += cu[j] - cv[j]; }
        // block exclusive scan of tot
        __shared__ int wsum[32];
        int x = tot;
        #pragma unroll
        for (int o = 1; o < 32; o <<= 1) {
            int y = __shfl_up_sync(0xffffffffu, x, o);
            if (lane >= o) x += y;
        }
        if (lane == 31) wsum[w] = x;
        __syncthreads();
        if (w == 0) {
            int v = wsum[lane];
            #pragma unroll
            for (int o = 1; o < 32; o <<= 1) {
                int y = __shfl_up_sync(0xffffffffu, v, o);
                if (lane >= o) v += y;
            }
            wsum[lane] = v;
        }
        __syncthreads();
        int texcl = x - tot + (w ? wsum[w-1] : 0);
        double acc = 0.0;
        #pragma unroll
        for (int j = 0; j < 4; ++j) {
            int excl = texcl + pre[j];
            if (((cu[j] | cv[j]) != 0) || (excl != 0)) {
                unsigned kb = (unsigned)(t*4 + j) << 20;
                double L = (double)keydec(kb);
                double R = (double)keydec(kb + 0x100000u);
                acc += fabs((double)excl * (R - L)
                            + (double)cu[j] * R - (double)su[j]
                            - (double)cv[j] * R + (double)sv[j]);
            }
        }
        // zero hist slices for next call
        reinterpret_cast<uint4*>(cp)[t] = make_uint4(0,0,0,0);
        reinterpret_cast<uint4*>(cg)[t] = make_uint4(0,0,0,0);
        reinterpret_cast<float4*>(sp)[t] = make_float4(0.f,0.f,0.f,0.f);
        reinterpret_cast<float4*>(sg)[t] = make_float4(0.f,0.f,0.f,0.f);
        // block-reduce acc (double)
        __shared__ double dsm[32];
        #pragma unroll
        for (int o = 16; o; o >>= 1) acc += __shfl_xor_sync(0xffffffffu, acc, o);
        if (lane == 0) dsm[w] = acc;
        __syncthreads();
        if (w == 0) {
            acc = dsm[lane];
            #pragma unroll
            for (int o = 16; o; o >>= 1) acc += __shfl_xor_sync(0xffffffffu, acc, o);
            if (t == 0) g_emd[b] = acc;
        }
    } else if (bx < 40) {
        uint4* m1v = reinterpret_cast<uint4*>(g_m1);
        float s = 0.f;
        for (int i = (bx-32)*1024 + t; i < B_*N_/4; i += 8*1024) {
            uint4 v = m1v[i];
            s += sqrtf(mindec(v.x)) + sqrtf(mindec(v.y))
               + sqrtf(mindec(v.z)) + sqrtf(mindec(v.w));
            m1v[i] = make_uint4(0,0,0,0);
        }
        s = blockReduceSum(s);
        if (t == 0) atomicAdd(&g_s1, (double)s);
    } else {
        uint4* m2v = reinterpret_cast<uint4*>(g_m2);
        float s = 0.f;
        for (int i = (bx-40)*1024 + t; i < N_*N_/4; i += 248*1024) {
            uint4 v = m2v[i];
            s += sqrtf(mindec(v.x)) + sqrtf(mindec(v.y))
               + sqrtf(mindec(v.z)) + sqrtf(mindec(v.w));
            m2v[i] = make_uint4(0,0,0,0);
        }
        s = blockReduceSum(s);
        if (t == 0) atomicAdd(&g_s2, (double)s);
    }
}

// ---------------- final combine (zeroes accumulators for next call) ----------------
__global__ void k_final(float* out) {
    int b = threadIdx.x;
    double mae  = g_mae / (double)TOT;
    double cham = g_s1 / (double)(B_*N_) + g_s2 / (double)(N_*N_);
    if (b < B_) out[b] = (float)(mae + cham + g_emd[b] / (double)NDF);
    __syncthreads();
    if (b == 0) { g_mae = 0.0; g_s1 = 0.0; g_s2 = 0.0; }
}

extern "C" void kernel_launch(void* const* d_in, const int* in_sizes, int n_in,
                              void* d_out, int out_size) {
    const float* pred   = (const float*)d_in[0];
    const float* target = (const float*)d_in[1];
    float* out = (float*)d_out;

    cudaFuncSetAttribute(k_chamfer, cudaFuncAttributeMaxDynamicSharedMemorySize, CHAM_SMEM);
    cudaFuncSetAttribute(k_fused,   cudaFuncAttributeMaxDynamicSharedMemorySize, FUSED_SMEM);

    k_fused<<<256, 256, FUSED_SMEM>>>(pred, target);
    k_chamfer<<<dim3(8, 8, 2), 512, CHAM_SMEM>>>();
    k_post<<<288, 1024>>>();
    k_final<<<1, 32>>>(out);
}

// round 15
// speedup vs baseline: 1.2828x; 1.0820x over previous
#include <cuda_runtime.h>
#include <cuda_bf16.h>
#include <cstdint>

#define B_  32
#define N_  1024
#define D_  128
#define NDF (N_*D_)          // 131072 per batch per tensor
#define TOT (B_*N_*D_)       // 4194304
#define NBUCK 4096           // 12-bit monotone-key prefix buckets

// ---------------- device scratch (zero-init == ready state; all self-cleaning) ----------------
__device__ float    g_normP[B_*N_];
__device__ float    g_normT[B_*N_];
__device__ unsigned g_m1[B_*N_];       // max of (0x7F800000 - bits(d^2)); 0 == +inf
__device__ unsigned g_m2[N_*N_];
__device__ double   g_mae, g_s1, g_s2;
__device__ double   g_emd[B_];
__device__ unsigned g_cntP[B_*NBUCK];
__device__ unsigned g_cntG[B_*NBUCK];
__device__ float    g_sumP[B_*NBUCK];
__device__ float    g_sumG[B_*NBUCK];
__device__ unsigned g_bfP[TOT/2];      // bf16x2 packed pred
__device__ unsigned g_bfG[TOT/2];      // bf16x2 packed target
__device__ unsigned g_done;            // k_post completion counter (self-resets)

// ---------------- helpers ----------------
__device__ __forceinline__ unsigned pack_bf16x2(float lo, float hi) {
    unsigned r;
    asm("cvt.rn.bf16x2.f32 %0, %1, %2;" : "=r"(r) : "f"(hi), "f"(lo));
    return r;
}
__device__ __forceinline__ float bf_lo(unsigned u) { return __uint_as_float(u << 16); }
__device__ __forceinline__ float bf_hi(unsigned u) { return __uint_as_float(u & 0xFFFF0000u); }

__device__ __forceinline__ void mma_bf16(float* c, const unsigned* a, const unsigned* b) {
    asm volatile(
        "mma.sync.aligned.m16n8k16.row.col.f32.bf16.bf16.f32 "
        "{%0,%1,%2,%3}, {%4,%5,%6,%7}, {%8,%9}, {%0,%1,%2,%3};\n"
        : "+f"(c[0]), "+f"(c[1]), "+f"(c[2]), "+f"(c[3])
        : "r"(a[0]), "r"(a[1]), "r"(a[2]), "r"(a[3]), "r"(b[0]), "r"(b[1]));
}
__device__ __forceinline__ void ldsm_x4(unsigned* r, uint32_t addr) {
    asm volatile("ldmatrix.sync.aligned.m8n8.x4.shared.b16 {%0,%1,%2,%3}, [%4];"
        : "=r"(r[0]), "=r"(r[1]), "=r"(r[2]), "=r"(r[3]) : "r"(addr));
}
__device__ __forceinline__ void cp_async8(uint32_t saddr, const void* g) {
    asm volatile("cp.async.ca.shared.global [%0], [%1], 8;" :: "r"(saddr), "l"(g));
}
__device__ __forceinline__ void cp_async4(uint32_t saddr, const void* g) {
    asm volatile("cp.async.ca.shared.global [%0], [%1], 4;" :: "r"(saddr), "l"(g));
}
#define CP_COMMIT()  asm volatile("cp.async.commit_group;")
#define CP_WAIT(n)   asm volatile("cp.async.wait_group %0;" :: "n"(n))

__device__ __forceinline__ float blockReduceSum(float v) {
    #pragma unroll
    for (int o = 16; o; o >>= 1) v += __shfl_xor_sync(0xffffffffu, v, o);
    __shared__ float sm[32];
    int lane = threadIdx.x & 31, w = threadIdx.x >> 5;
    int nw = (blockDim.x + 31) >> 5;
    if (lane == 0) sm[w] = v;
    __syncthreads();
    if (w == 0) {
        v = (lane < nw) ? sm[lane] : 0.f;
        #pragma unroll
        for (int o = 16; o; o >>= 1) v += __shfl_xor_sync(0xffffffffu, v, o);
    }
    return v;  // valid on thread 0
}
__device__ __forceinline__ unsigned keyenc(float v) {
    unsigned u = __float_as_uint(v);
    return (u & 0x80000000u) ? ~u : (u | 0x80000000u);
}
__device__ __forceinline__ float keydec(unsigned u) {
    unsigned bits = (u & 0x80000000u) ? (u ^ 0x80000000u) : ~u;
    return __uint_as_float(bits);
}
// negated-min encoding: larger == smaller d^2; 0 == +inf (matches static zero-init)
__device__ __forceinline__ unsigned minenc(float d2) {
    return 0x7F800000u - __float_as_uint(d2);
}
__device__ __forceinline__ float mindec(unsigned t) {
    return __uint_as_float(0x7F800000u - t);
}

// ---- fused MAE + bf16 conversion + norms + smem-privatized EMD histograms ----
#define FUSED_SMEM (4*NBUCK*4)   // 64 KB

__global__ void __launch_bounds__(256)
k_fused(const float* __restrict__ pred, const float* __restrict__ target) {
    extern __shared__ unsigned sh[];
    unsigned* scP = sh;                 // [NBUCK]
    float*    ssP = (float*)(sh + NBUCK);
    unsigned* scG = sh + 2*NBUCK;
    float*    ssG = (float*)(sh + 3*NBUCK);

    const int t = threadIdx.x;
    const int lane = t & 31, w = t >> 5;
    const int batch = blockIdx.x >> 3;
    const int chunk = blockIdx.x & 7;
    const int row0 = batch * N_ + chunk * 128;

    for (int i = t; i < NBUCK; i += 256) {
        scP[i] = 0u; ssP[i] = 0.f; scG[i] = 0u; ssG[i] = 0.f;
    }
    __syncthreads();

    uint2* bfP2 = reinterpret_cast<uint2*>(g_bfP);
    uint2* bfG2 = reinterpret_cast<uint2*>(g_bfG);

    float macc = 0.f;
    for (int pass = 0; pass < 16; ++pass) {
        int row = row0 + pass*8 + w;
        float4 p  = reinterpret_cast<const float4*>(pred)[row*32 + lane];
        float4 tg = reinterpret_cast<const float4*>(target)[row*32 + lane];
        macc += fabsf(p.x-tg.x)+fabsf(p.y-tg.y)+fabsf(p.z-tg.z)+fabsf(p.w-tg.w);
        // bf16 scratch
        uint2 up, ug;
        up.x = pack_bf16x2(p.x, p.y);
        up.y = pack_bf16x2(p.z, p.w);
        ug.x = pack_bf16x2(tg.x, tg.y);
        ug.y = pack_bf16x2(tg.z, tg.w);
        bfP2[row*32 + lane] = up;
        bfG2[row*32 + lane] = ug;
        // norms of bf16-rounded values (consistent with chamfer MMA inputs)
        {
            float a0 = bf_lo(up.x), a1 = bf_hi(up.x), a2 = bf_lo(up.y), a3 = bf_hi(up.y);
            float b0 = bf_lo(ug.x), b1 = bf_hi(ug.x), b2 = bf_lo(ug.y), b3 = bf_hi(ug.y);
            float np = a0*a0 + a1*a1 + a2*a2 + a3*a3;
            float nt = b0*b0 + b1*b1 + b2*b2 + b3*b3;
            #pragma unroll
            for (int o = 16; o; o >>= 1) {
                np += __shfl_xor_sync(0xffffffffu, np, o);
                nt += __shfl_xor_sync(0xffffffffu, nt, o);
            }
            if (lane == 0) { g_normP[row] = np; g_normT[row] = nt; }
        }
        // histograms (exact f32 values)
        atomicAdd(&scP[keyenc(p.x)  >> 20], 1u); atomicAdd(&ssP[keyenc(p.x)  >> 20], p.x);
        atomicAdd(&scP[keyenc(p.y)  >> 20], 1u); atomicAdd(&ssP[keyenc(p.y)  >> 20], p.y);
        atomicAdd(&scP[keyenc(p.z)  >> 20], 1u); atomicAdd(&ssP[keyenc(p.z)  >> 20], p.z);
        atomicAdd(&scP[keyenc(p.w)  >> 20], 1u); atomicAdd(&ssP[keyenc(p.w)  >> 20], p.w);
        atomicAdd(&scG[keyenc(tg.x) >> 20], 1u); atomicAdd(&ssG[keyenc(tg.x) >> 20], tg.x);
        atomicAdd(&scG[keyenc(tg.y) >> 20], 1u); atomicAdd(&ssG[keyenc(tg.y) >> 20], tg.y);
        atomicAdd(&scG[keyenc(tg.z) >> 20], 1u); atomicAdd(&ssG[keyenc(tg.z) >> 20], tg.z);
        atomicAdd(&scG[keyenc(tg.w) >> 20], 1u); atomicAdd(&ssG[keyenc(tg.w) >> 20], tg.w);
    }

    // MAE reduce
    #pragma unroll
    for (int o = 16; o; o >>= 1) macc += __shfl_xor_sync(0xffffffffu, macc, o);
    __shared__ float bsum;
    if (t == 0) bsum = 0.f;
    __syncthreads();
    if (lane == 0) atomicAdd(&bsum, macc);
    __syncthreads();
    if (t == 0) atomicAdd(&g_mae, (double)bsum);

    // merge populated buckets to global
    const size_t boff = (size_t)batch * NBUCK;
    for (int i = t; i < NBUCK; i += 256) {
        unsigned c = scP[i];
        if (c) { atomicAdd(&g_cntP[boff+i], c); atomicAdd(&g_sumP[boff+i], ssP[i]); }
        c = scG[i];
        if (c) { atomicAdd(&g_cntG[boff+i], c); atomicAdd(&g_sumG[boff+i], ssG[i]); }
    }
}

// ---- chamfer: bf16 MMA + ldmatrix + cp.async double buffering, single wave ----
#define TI 128
#define TJ 128
#define BB 16
#define SROW 68              // u32 stride/row: 272B == 4 banks (mod 32), LDSM conflict-free
#define ABUF (128*SROW)      // u32 per tile
#define CHAM_SMEM ((4*ABUF + 512) * 4)   // 2 bufs x (A+B) + 2 x 256 norm floats

__global__ void __launch_bounds__(512, 1)
k_chamfer() {
    extern __shared__ unsigned smem_u[];

    const int tid  = threadIdx.x;
    const int lane = tid & 31;
    const int warp = tid >> 5;           // 0..15
    const int wi = warp >> 2;            // 0..3
    const int wj = warp & 3;             // 0..3
    const int g  = lane >> 2;            // 0..7
    const int cc = lane & 3;             // 0..3

    const int i0 = blockIdx.x * TI;
    const int j0 = blockIdx.y * TJ;
    const int b0 = blockIdx.z * BB;

    const uint2* bfP2 = reinterpret_cast<const uint2*>(g_bfP);
    const uint2* bfG2 = reinterpret_cast<const uint2*>(g_bfG);

    uint32_t sbase = (uint32_t)__cvta_generic_to_shared(smem_u);

    // ldmatrix per-lane offsets (relative to tile start, bytes)
    uint32_t aOff[2], bOff[2];
    #pragma unroll
    for (int mt = 0; mt < 2; ++mt) {
        int row = wi*32 + mt*16 + (lane & 15);
        aOff[mt] = (row*SROW + (lane >> 4)*4) * 4;
    }
    #pragma unroll
    for (int p = 0; p < 2; ++p) {
        int q = lane >> 3;                                  // 0..3
        int jr = wj*32 + (p*2 + (q >> 1))*8 + (lane & 7);   // two n8 tiles per LDSM
        bOff[p] = (jr*SROW + (q & 1)*4) * 4;
    }

    // async tile loader: batch bi -> buffer buf
    auto issue_load = [&](int bi, int buf) {
        const int b = b0 + bi;
        uint32_t abase = sbase + (buf*2*ABUF) * 4;
        uint32_t bbase = abase + ABUF * 4;
        #pragma unroll
        for (int r = 0; r < 8; ++r) {
            int row = r*16 + warp;
            cp_async8(abase + (row*SROW + lane*2)*4, &bfP2[((size_t)b*N_ + i0 + row)*32 + lane]);
            cp_async8(bbase + (row*SROW + lane*2)*4, &bfG2[((size_t)b*N_ + j0 + row)*32 + lane]);
        }
        uint32_t nbase = sbase + (4*ABUF + buf*256) * 4;
        if (tid < 128)       cp_async4(nbase + tid*4, &g_normP[b*N_ + i0 + tid]);
        else if (tid < 256)  cp_async4(nbase + tid*4, &g_normT[b*N_ + j0 + (tid-128)]);
        CP_COMMIT();
    };

    float dmin[2][4][4];
    #pragma unroll
    for (int mt = 0; mt < 2; mt++)
        #pragma unroll
        for (int nt = 0; nt < 4; nt++)
            #pragma unroll
            for (int q = 0; q < 4; q++) dmin[mt][nt][q] = 3.4e38f;

    issue_load(0, 0);

    for (int bi = 0; bi < BB; ++bi) {
        const int b = b0 + bi;
        const int buf = bi & 1;
        if (bi + 1 < BB) { issue_load(bi + 1, (bi + 1) & 1); CP_WAIT(1); }
        else             { CP_WAIT(0); }
        __syncthreads();

        const uint32_t tilebase = sbase + (buf*2*ABUF)*4;
        const float* sNp = (const float*)(smem_u + 4*ABUF + buf*256);
        const float* sNt = sNp + 128;

        float acc[2][4][4];
        #pragma unroll
        for (int mt = 0; mt < 2; mt++)
            #pragma unroll
            for (int nt = 0; nt < 4; nt++)
                #pragma unroll
                for (int q = 0; q < 4; q++) acc[mt][nt][q] = 0.f;

        #pragma unroll
        for (int ks = 0; ks < 8; ++ks) {
            unsigned a[2][4], bf[2][4];
            ldsm_x4(a[0],  tilebase + aOff[0] + ks*32);
            ldsm_x4(a[1],  tilebase + aOff[1] + ks*32);
            ldsm_x4(bf[0], tilebase + ABUF*4 + bOff[0] + ks*32);
            ldsm_x4(bf[1], tilebase + ABUF*4 + bOff[1] + ks*32);
            #pragma unroll
            for (int mt = 0; mt < 2; ++mt)
                #pragma unroll
                for (int nt = 0; nt < 4; ++nt) {
                    unsigned bb[2] = { bf[nt>>1][(nt&1)*2], bf[nt>>1][(nt&1)*2 + 1] };
                    mma_bf16(acc[mt][nt], a[mt], bb);
                }
        }

        float nP[2][2];
        #pragma unroll
        for (int mt = 0; mt < 2; ++mt) {
            int r0 = wi*32 + mt*16 + g;
            nP[mt][0] = sNp[r0];
            nP[mt][1] = sNp[r0+8];
        }
        #pragma unroll
        for (int nt = 0; nt < 4; ++nt) {
            int cA = wj*32 + nt*8 + 2*cc;
            float nt0 = sNt[cA], nt1 = sNt[cA+1];
            float cm0 = 3.4e38f, cm1 = 3.4e38f;
            #pragma unroll
            for (int mt = 0; mt < 2; ++mt) {
                float s0 = fmaxf(fmaf(-2.f, acc[mt][nt][0], nP[mt][0] + nt0), 1e-12f);
                float s1 = fmaxf(fmaf(-2.f, acc[mt][nt][1], nP[mt][0] + nt1), 1e-12f);
                float s2 = fmaxf(fmaf(-2.f, acc[mt][nt][2], nP[mt][1] + nt0), 1e-12f);
                float s3 = fmaxf(fmaf(-2.f, acc[mt][nt][3], nP[mt][1] + nt1), 1e-12f);
                dmin[mt][nt][0] = fminf(dmin[mt][nt][0], s0);
                dmin[mt][nt][1] = fminf(dmin[mt][nt][1], s1);
                dmin[mt][nt][2] = fminf(dmin[mt][nt][2], s2);
                dmin[mt][nt][3] = fminf(dmin[mt][nt][3], s3);
                cm0 = fminf(cm0, fminf(s0, s2));
                cm1 = fminf(cm1, fminf(s1, s3));
            }
            #pragma unroll
            for (int o = 4; o <= 16; o <<= 1) {
                cm0 = fminf(cm0, __shfl_xor_sync(0xffffffffu, cm0, o));
                cm1 = fminf(cm1, __shfl_xor_sync(0xffffffffu, cm1, o));
            }
            if (g == 0) {
                atomicMax(&g_m1[b*N_ + j0 + cA],     minenc(cm0));
                atomicMax(&g_m1[b*N_ + j0 + cA + 1], minenc(cm1));
            }
        }
        __syncthreads();   // protect buffer reuse by next issue_load
    }

    #pragma unroll
    for (int mt = 0; mt < 2; ++mt) {
        int r0 = i0 + wi*32 + mt*16 + g;
        #pragma unroll
        for (int nt = 0; nt < 4; ++nt) {
            int cA = j0 + wj*32 + nt*8 + 2*cc;
            atomicMax(&g_m2[r0*N_ + cA],       minenc(dmin[mt][nt][0]));
            atomicMax(&g_m2[r0*N_ + cA + 1],   minenc(dmin[mt][nt][1]));
            atomicMax(&g_m2[(r0+8)*N_ + cA],   minenc(dmin[mt][nt][2]));
            atomicMax(&g_m2[(r0+8)*N_ + cA+1], minenc(dmin[mt][nt][3]));
        }
    }
}

// ---- post pass: EMD CDF (blocks 0..31), m1 sqrt-sum (32..39), m2 sqrt-sum (40..287),
//      last finishing block combines everything into out. Self-cleaning. ----
__global__ void __launch_bounds__(1024) k_post(float* __restrict__ out) {
    const int bx = blockIdx.x;
    const int t = threadIdx.x, lane = t & 31, w = t >> 5;
    if (bx < 32) {
        // single-pass CDF: thread t owns buckets 4t..4t+3
        const int b = bx;
        unsigned* cp = g_cntP + (size_t)b * NBUCK;
        unsigned* cg = g_cntG + (size_t)b * NBUCK;
        float*    sp = g_sumP + (size_t)b * NBUCK;
        float*    sg = g_sumG + (size_t)b * NBUCK;
        uint4 cu4 = reinterpret_cast<uint4*>(cp)[t];
        uint4 cv4 = reinterpret_cast<uint4*>(cg)[t];
        float4 su4 = reinterpret_cast<float4*>(sp)[t];
        float4 sv4 = reinterpret_cast<float4*>(sg)[t];
        int cu[4] = {(int)cu4.x,(int)cu4.y,(int)cu4.z,(int)cu4.w};
        int cv[4] = {(int)cv4.x,(int)cv4.y,(int)cv4.z,(int)cv4.w};
        float su[4] = {su4.x,su4.y,su4.z,su4.w};
        float sv[4] = {sv4.x,sv4.y,sv4.z,sv4.w};
        int pre[4]; int tot = 0;
        #pragma unroll
        for (int j = 0; j < 4; ++j) { pre[j] = tot; tot += cu[j] - cv[j]; }
        __shared__ int wsum[32];
        int x = tot;
        #pragma unroll
        for (int o = 1; o < 32; o <<= 1) {
            int y = __shfl_up_sync(0xffffffffu, x, o);
            if (lane >= o) x += y;
        }
        if (lane == 31) wsum[w] = x;
        __syncthreads();
        if (w == 0) {
            int v = wsum[lane];
            #pragma unroll
            for (int o = 1; o < 32; o <<= 1) {
                int y = __shfl_up_sync(0xffffffffu, v, o);
                if (lane >= o) v += y;
            }
            wsum[lane] = v;
        }
        __syncthreads();
        int texcl = x - tot + (w ? wsum[w-1] : 0);
        double acc = 0.0;
        #pragma unroll
        for (int j = 0; j < 4; ++j) {
            int excl = texcl + pre[j];
            if (((cu[j] | cv[j]) != 0) || (excl != 0)) {
                unsigned kb = (unsigned)(t*4 + j) << 20;
                double L = (double)keydec(kb);
                double R = (double)keydec(kb + 0x100000u);
                acc += fabs((double)excl * (R - L)
                            + (double)cu[j] * R - (double)su[j]
                            - (double)cv[j] * R + (double)sv[j]);
            }
        }
        reinterpret_cast<uint4*>(cp)[t] = make_uint4(0,0,0,0);
        reinterpret_cast<uint4*>(cg)[t] = make_uint4(0,0,0,0);
        reinterpret_cast<float4*>(sp)[t] = make_float4(0.f,0.f,0.f,0.f);
        reinterpret_cast<float4*>(sg)[t] = make_float4(0.f,0.f,0.f,0.f);
        __shared__ double dsm[32];
        #pragma unroll
        for (int o = 16; o; o >>= 1) acc += __shfl_xor_sync(0xffffffffu, acc, o);
        if (lane == 0) dsm[w] = acc;
        __syncthreads();
        if (w == 0) {
            acc = dsm[lane];
            #pragma unroll
            for (int o = 16; o; o >>= 1) acc += __shfl_xor_sync(0xffffffffu, acc, o);
            if (t == 0) g_emd[b] = acc;
        }
    } else if (bx < 40) {
        uint4* m1v = reinterpret_cast<uint4*>(g_m1);
        float s = 0.f;
        for (int i = (bx-32)*1024 + t; i < B_*N_/4; i += 8*1024) {
            uint4 v = m1v[i];
            s += sqrtf(mindec(v.x)) + sqrtf(mindec(v.y))
               + sqrtf(mindec(v.z)) + sqrtf(mindec(v.w));
            m1v[i] = make_uint4(0,0,0,0);
        }
        s = blockReduceSum(s);
        if (t == 0) atomicAdd(&g_s1, (double)s);
    } else {
        uint4* m2v = reinterpret_cast<uint4*>(g_m2);
        float s = 0.f;
        for (int i = (bx-40)*1024 + t; i < N_*N_/4; i += 248*1024) {
            uint4 v = m2v[i];
            s += sqrtf(mindec(v.x)) + sqrtf(mindec(v.y))
               + sqrtf(mindec(v.z)) + sqrtf(mindec(v.w));
            m2v[i] = make_uint4(0,0,0,0);
        }
        s = blockReduceSum(s);
        if (t == 0) atomicAdd(&g_s2, (double)s);
    }

    // last finishing block combines and self-cleans accumulators
    __syncthreads();
    __threadfence();
    __shared__ unsigned amlast;
    if (t == 0) amlast = (atomicAdd(&g_done, 1u) == 287u) ? 1u : 0u;
    __syncthreads();
    if (amlast) {
        if (t < B_) {
            double mae  = g_mae / (double)TOT;
            double cham = g_s1 / (double)(B_*N_) + g_s2 / (double)(N_*N_);
            out[t] = (float)(mae + cham + g_emd[t] / (double)NDF);
        }
        __syncthreads();
        if (t == 0) { g_mae = 0.0; g_s1 = 0.0; g_s2 = 0.0; g_done = 0u; }
    }
}

extern "C" void kernel_launch(void* const* d_in, const int* in_sizes, int n_in,
                              void* d_out, int out_size) {
    const float* pred   = (const float*)d_in[0];
    const float* target = (const float*)d_in[1];
    float* out = (float*)d_out;

    cudaFuncSetAttribute(k_chamfer, cudaFuncAttributeMaxDynamicSharedMemorySize, CHAM_SMEM);
    cudaFuncSetAttribute(k_fused,   cudaFuncAttributeMaxDynamicSharedMemorySize, FUSED_SMEM);

    k_fused<<<256, 256, FUSED_SMEM>>>(pred, target);
    k_chamfer<<<dim3(8, 8, 2), 512, CHAM_SMEM>>>();
    k_post<<<288, 1024>>>(out);
}

// round 16
// speedup vs baseline: 1.3315x; 1.0380x over previous
#include <cuda_runtime.h>
#include <cuda_bf16.h>
#include <cstdint>

#define B_  32
#define N_  1024
#define D_  128
#define NDF (N_*D_)          // 131072 per batch per tensor
#define TOT (B_*N_*D_)       // 4194304
#define NBUCK 4096           // 12-bit monotone-key prefix buckets

// ---------------- device scratch (zero-init == ready state; all self-cleaning) ----------------
__device__ float    g_normP[B_*N_];
__device__ float    g_normT[B_*N_];
__device__ unsigned g_m1[B_*N_];       // max of (0x7F800000 - bits(d^2)); 0 == +inf
__device__ unsigned g_m2[N_*N_];
__device__ double   g_mae, g_s1, g_s2;
__device__ double   g_emd[B_];
__device__ unsigned g_cntP[B_*NBUCK];
__device__ unsigned g_cntG[B_*NBUCK];
__device__ float    g_sumP[B_*NBUCK];
__device__ float    g_sumG[B_*NBUCK];
__device__ unsigned g_bfP[TOT/2];      // bf16x2 packed pred
__device__ unsigned g_bfG[TOT/2];      // bf16x2 packed target
__device__ unsigned g_done;            // k_post completion counter (self-resets)

// ---------------- helpers ----------------
__device__ __forceinline__ unsigned pack_bf16x2(float lo, float hi) {
    unsigned r;
    asm("cvt.rn.bf16x2.f32 %0, %1, %2;" : "=r"(r) : "f"(hi), "f"(lo));
    return r;
}
__device__ __forceinline__ float bf_lo(unsigned u) { return __uint_as_float(u << 16); }
__device__ __forceinline__ float bf_hi(unsigned u) { return __uint_as_float(u & 0xFFFF0000u); }

__device__ __forceinline__ void mma_bf16(float* c, const unsigned* a, const unsigned* b) {
    asm volatile(
        "mma.sync.aligned.m16n8k16.row.col.f32.bf16.bf16.f32 "
        "{%0,%1,%2,%3}, {%4,%5,%6,%7}, {%8,%9}, {%0,%1,%2,%3};\n"
        : "+f"(c[0]), "+f"(c[1]), "+f"(c[2]), "+f"(c[3])
        : "r"(a[0]), "r"(a[1]), "r"(a[2]), "r"(a[3]), "r"(b[0]), "r"(b[1]));
}
__device__ __forceinline__ void ldsm_x4(unsigned* r, uint32_t addr) {
    asm volatile("ldmatrix.sync.aligned.m8n8.x4.shared.b16 {%0,%1,%2,%3}, [%4];"
        : "=r"(r[0]), "=r"(r[1]), "=r"(r[2]), "=r"(r[3]) : "r"(addr));
}
__device__ __forceinline__ void cp_async8(uint32_t saddr, const void* g) {
    asm volatile("cp.async.ca.shared.global [%0], [%1], 8;" :: "r"(saddr), "l"(g));
}
__device__ __forceinline__ void cp_async4(uint32_t saddr, const void* g) {
    asm volatile("cp.async.ca.shared.global [%0], [%1], 4;" :: "r"(saddr), "l"(g));
}
#define CP_COMMIT()  asm volatile("cp.async.commit_group;")
#define CP_WAIT(n)   asm volatile("cp.async.wait_group %0;" :: "n"(n))

__device__ __forceinline__ float blockReduceSum(float v) {
    #pragma unroll
    for (int o = 16; o; o >>= 1) v += __shfl_xor_sync(0xffffffffu, v, o);
    __shared__ float sm[32];
    int lane = threadIdx.x & 31, w = threadIdx.x >> 5;
    int nw = (blockDim.x + 31) >> 5;
    if (lane == 0) sm[w] = v;
    __syncthreads();
    if (w == 0) {
        v = (lane < nw) ? sm[lane] : 0.f;
        #pragma unroll
        for (int o = 16; o; o >>= 1) v += __shfl_xor_sync(0xffffffffu, v, o);
    }
    return v;  // valid on thread 0
}
__device__ __forceinline__ unsigned keyenc(float v) {
    unsigned u = __float_as_uint(v);
    return (u & 0x80000000u) ? ~u : (u | 0x80000000u);
}
__device__ __forceinline__ float keydec(unsigned u) {
    unsigned bits = (u & 0x80000000u) ? (u ^ 0x80000000u) : ~u;
    return __uint_as_float(bits);
}
// negated-min encoding: larger == smaller d^2; 0 == +inf (matches static zero-init)
__device__ __forceinline__ unsigned minenc(float d2) {
    return 0x7F800000u - __float_as_uint(d2);
}
__device__ __forceinline__ float mindec(unsigned t) {
    return __uint_as_float(0x7F800000u - t);
}

// ---- fused MAE + bf16 conversion + norms + smem-privatized EMD histograms ----
// 512 threads/block for occupancy (latency-bound atomics); block owns 128 rows.
#define FUSED_SMEM (4*NBUCK*4)   // 64 KB

__global__ void __launch_bounds__(512)
k_fused(const float* __restrict__ pred, const float* __restrict__ target) {
    extern __shared__ unsigned sh[];
    unsigned* scP = sh;                 // [NBUCK]
    float*    ssP = (float*)(sh + NBUCK);
    unsigned* scG = sh + 2*NBUCK;
    float*    ssG = (float*)(sh + 3*NBUCK);

    const int t = threadIdx.x;
    const int lane = t & 31, w = t >> 5;          // 16 warps
    const int batch = blockIdx.x >> 3;
    const int chunk = blockIdx.x & 7;
    const int row0 = batch * N_ + chunk * 128;

    for (int i = t; i < NBUCK; i += 512) {
        scP[i] = 0u; ssP[i] = 0.f; scG[i] = 0u; ssG[i] = 0.f;
    }
    __syncthreads();

    uint2* bfP2 = reinterpret_cast<uint2*>(g_bfP);
    uint2* bfG2 = reinterpret_cast<uint2*>(g_bfG);

    float macc = 0.f;
    #pragma unroll
    for (int pass = 0; pass < 8; ++pass) {
        int row = row0 + pass*16 + w;
        float4 p  = reinterpret_cast<const float4*>(pred)[row*32 + lane];
        float4 tg = reinterpret_cast<const float4*>(target)[row*32 + lane];
        macc += fabsf(p.x-tg.x)+fabsf(p.y-tg.y)+fabsf(p.z-tg.z)+fabsf(p.w-tg.w);
        // bf16 scratch
        uint2 up, ug;
        up.x = pack_bf16x2(p.x, p.y);
        up.y = pack_bf16x2(p.z, p.w);
        ug.x = pack_bf16x2(tg.x, tg.y);
        ug.y = pack_bf16x2(tg.z, tg.w);
        bfP2[row*32 + lane] = up;
        bfG2[row*32 + lane] = ug;
        // norms of bf16-rounded values (consistent with chamfer MMA inputs)
        {
            float a0 = bf_lo(up.x), a1 = bf_hi(up.x), a2 = bf_lo(up.y), a3 = bf_hi(up.y);
            float b0 = bf_lo(ug.x), b1 = bf_hi(ug.x), b2 = bf_lo(ug.y), b3 = bf_hi(ug.y);
            float np = a0*a0 + a1*a1 + a2*a2 + a3*a3;
            float nt = b0*b0 + b1*b1 + b2*b2 + b3*b3;
            #pragma unroll
            for (int o = 16; o; o >>= 1) {
                np += __shfl_xor_sync(0xffffffffu, np, o);
                nt += __shfl_xor_sync(0xffffffffu, nt, o);
            }
            if (lane == 0) { g_normP[row] = np; g_normT[row] = nt; }
        }
        // histograms (exact f32 values)
        atomicAdd(&scP[keyenc(p.x)  >> 20], 1u); atomicAdd(&ssP[keyenc(p.x)  >> 20], p.x);
        atomicAdd(&scP[keyenc(p.y)  >> 20], 1u); atomicAdd(&ssP[keyenc(p.y)  >> 20], p.y);
        atomicAdd(&scP[keyenc(p.z)  >> 20], 1u); atomicAdd(&ssP[keyenc(p.z)  >> 20], p.z);
        atomicAdd(&scP[keyenc(p.w)  >> 20], 1u); atomicAdd(&ssP[keyenc(p.w)  >> 20], p.w);
        atomicAdd(&scG[keyenc(tg.x) >> 20], 1u); atomicAdd(&ssG[keyenc(tg.x) >> 20], tg.x);
        atomicAdd(&scG[keyenc(tg.y) >> 20], 1u); atomicAdd(&ssG[keyenc(tg.y) >> 20], tg.y);
        atomicAdd(&scG[keyenc(tg.z) >> 20], 1u); atomicAdd(&ssG[keyenc(tg.z) >> 20], tg.z);
        atomicAdd(&scG[keyenc(tg.w) >> 20], 1u); atomicAdd(&ssG[keyenc(tg.w) >> 20], tg.w);
    }

    // MAE reduce
    #pragma unroll
    for (int o = 16; o; o >>= 1) macc += __shfl_xor_sync(0xffffffffu, macc, o);
    __shared__ float bsum;
    if (t == 0) bsum = 0.f;
    __syncthreads();
    if (lane == 0) atomicAdd(&bsum, macc);
    __syncthreads();
    if (t == 0) atomicAdd(&g_mae, (double)bsum);

    // merge populated buckets to global
    const size_t boff = (size_t)batch * NBUCK;
    for (int i = t; i < NBUCK; i += 512) {
        unsigned c = scP[i];
        if (c) { atomicAdd(&g_cntP[boff+i], c); atomicAdd(&g_sumP[boff+i], ssP[i]); }
        c = scG[i];
        if (c) { atomicAdd(&g_cntG[boff+i], c); atomicAdd(&g_sumG[boff+i], ssG[i]); }
    }
}

// ---- chamfer: bf16 MMA + ldmatrix + cp.async double buffering, single wave ----
#define TI 128
#define TJ 128
#define BB 16
#define SROW 68              // u32 stride/row: 272B == 4 banks (mod 32), LDSM conflict-free
#define ABUF (128*SROW)      // u32 per tile
#define CHAM_SMEM ((4*ABUF + 512) * 4)   // 2 bufs x (A+B) + 2 x 256 norm floats

__global__ void __launch_bounds__(512, 1)
k_chamfer() {
    extern __shared__ unsigned smem_u[];

    const int tid  = threadIdx.x;
    const int lane = tid & 31;
    const int warp = tid >> 5;           // 0..15
    const int wi = warp >> 2;            // 0..3
    const int wj = warp & 3;             // 0..3
    const int g  = lane >> 2;            // 0..7
    const int cc = lane & 3;             // 0..3

    const int i0 = blockIdx.x * TI;
    const int j0 = blockIdx.y * TJ;
    const int b0 = blockIdx.z * BB;

    const uint2* bfP2 = reinterpret_cast<const uint2*>(g_bfP);
    const uint2* bfG2 = reinterpret_cast<const uint2*>(g_bfG);

    uint32_t sbase = (uint32_t)__cvta_generic_to_shared(smem_u);

    // ldmatrix per-lane offsets (relative to tile start, bytes)
    uint32_t aOff[2], bOff[2];
    #pragma unroll
    for (int mt = 0; mt < 2; ++mt) {
        int row = wi*32 + mt*16 + (lane & 15);
        aOff[mt] = (row*SROW + (lane >> 4)*4) * 4;
    }
    #pragma unroll
    for (int p = 0; p < 2; ++p) {
        int q = lane >> 3;                                  // 0..3
        int jr = wj*32 + (p*2 + (q >> 1))*8 + (lane & 7);   // two n8 tiles per LDSM
        bOff[p] = (jr*SROW + (q & 1)*4) * 4;
    }

    // async tile loader: batch bi -> buffer buf
    auto issue_load = [&](int bi, int buf) {
        const int b = b0 + bi;
        uint32_t abase = sbase + (buf*2*ABUF) * 4;
        uint32_t bbase = abase + ABUF * 4;
        #pragma unroll
        for (int r = 0; r < 8; ++r) {
            int row = r*16 + warp;
            cp_async8(abase + (row*SROW + lane*2)*4, &bfP2[((size_t)b*N_ + i0 + row)*32 + lane]);
            cp_async8(bbase + (row*SROW + lane*2)*4, &bfG2[((size_t)b*N_ + j0 + row)*32 + lane]);
        }
        uint32_t nbase = sbase + (4*ABUF + buf*256) * 4;
        if (tid < 128)       cp_async4(nbase + tid*4, &g_normP[b*N_ + i0 + tid]);
        else if (tid < 256)  cp_async4(nbase + tid*4, &g_normT[b*N_ + j0 + (tid-128)]);
        CP_COMMIT();
    };

    float dmin[2][4][4];
    #pragma unroll
    for (int mt = 0; mt < 2; mt++)
        #pragma unroll
        for (int nt = 0; nt < 4; nt++)
            #pragma unroll
            for (int q = 0; q < 4; q++) dmin[mt][nt][q] = 3.4e38f;

    issue_load(0, 0);

    for (int bi = 0; bi < BB; ++bi) {
        const int b = b0 + bi;
        const int buf = bi & 1;
        if (bi + 1 < BB) { issue_load(bi + 1, (bi + 1) & 1); CP_WAIT(1); }
        else             { CP_WAIT(0); }
        __syncthreads();

        const uint32_t tilebase = sbase + (buf*2*ABUF)*4;
        const float* sNp = (const float*)(smem_u + 4*ABUF + buf*256);
        const float* sNt = sNp + 128;

        float acc[2][4][4];
        #pragma unroll
        for (int mt = 0; mt < 2; mt++)
            #pragma unroll
            for (int nt = 0; nt < 4; nt++)
                #pragma unroll
                for (int q = 0; q < 4; q++) acc[mt][nt][q] = 0.f;

        #pragma unroll
        for (int ks = 0; ks < 8; ++ks) {
            unsigned a[2][4], bf[2][4];
            ldsm_x4(a[0],  tilebase + aOff[0] + ks*32);
            ldsm_x4(a[1],  tilebase + aOff[1] + ks*32);
            ldsm_x4(bf[0], tilebase + ABUF*4 + bOff[0] + ks*32);
            ldsm_x4(bf[1], tilebase + ABUF*4 + bOff[1] + ks*32);
            #pragma unroll
            for (int mt = 0; mt < 2; ++mt)
                #pragma unroll
                for (int nt = 0; nt < 4; ++nt) {
                    unsigned bb[2] = { bf[nt>>1][(nt&1)*2], bf[nt>>1][(nt&1)*2 + 1] };
                    mma_bf16(acc[mt][nt], a[mt], bb);
                }
        }

        float nP[2][2];
        #pragma unroll
        for (int mt = 0; mt < 2; ++mt) {
            int r0 = wi*32 + mt*16 + g;
            nP[mt][0] = sNp[r0];
            nP[mt][1] = sNp[r0+8];
        }
        #pragma unroll
        for (int nt = 0; nt < 4; ++nt) {
            int cA = wj*32 + nt*8 + 2*cc;
            float nt0 = sNt[cA], nt1 = sNt[cA+1];
            float cm0 = 3.4e38f, cm1 = 3.4e38f;
            #pragma unroll
            for (int mt = 0; mt < 2; ++mt) {
                float s0 = fmaxf(fmaf(-2.f, acc[mt][nt][0], nP[mt][0] + nt0), 1e-12f);
                float s1 = fmaxf(fmaf(-2.f, acc[mt][nt][1], nP[mt][0] + nt1), 1e-12f);
                float s2 = fmaxf(fmaf(-2.f, acc[mt][nt][2], nP[mt][1] + nt0), 1e-12f);
                float s3 = fmaxf(fmaf(-2.f, acc[mt][nt][3], nP[mt][1] + nt1), 1e-12f);
                dmin[mt][nt][0] = fminf(dmin[mt][nt][0], s0);
                dmin[mt][nt][1] = fminf(dmin[mt][nt][1], s1);
                dmin[mt][nt][2] = fminf(dmin[mt][nt][2], s2);
                dmin[mt][nt][3] = fminf(dmin[mt][nt][3], s3);
                cm0 = fminf(cm0, fminf(s0, s2));
                cm1 = fminf(cm1, fminf(s1, s3));
            }
            #pragma unroll
            for (int o = 4; o <= 16; o <<= 1) {
                cm0 = fminf(cm0, __shfl_xor_sync(0xffffffffu, cm0, o));
                cm1 = fminf(cm1, __shfl_xor_sync(0xffffffffu, cm1, o));
            }
            if (g == 0) {
                atomicMax(&g_m1[b*N_ + j0 + cA],     minenc(cm0));
                atomicMax(&g_m1[b*N_ + j0 + cA + 1], minenc(cm1));
            }
        }
        __syncthreads();   // protect buffer reuse by next issue_load
    }

    #pragma unroll
    for (int mt = 0; mt < 2; ++mt) {
        int r0 = i0 + wi*32 + mt*16 + g;
        #pragma unroll
        for (int nt = 0; nt < 4; ++nt) {
            int cA = j0 + wj*32 + nt*8 + 2*cc;
            atomicMax(&g_m2[r0*N_ + cA],       minenc(dmin[mt][nt][0]));
            atomicMax(&g_m2[r0*N_ + cA + 1],   minenc(dmin[mt][nt][1]));
            atomicMax(&g_m2[(r0+8)*N_ + cA],   minenc(dmin[mt][nt][2]));
            atomicMax(&g_m2[(r0+8)*N_ + cA+1], minenc(dmin[mt][nt][3]));
        }
    }
}

// ---- post pass: EMD CDF (blocks 0..31), m1 sqrt-sum (32..39), m2 sqrt-sum (40..287),
//      last finishing block combines everything into out. Self-cleaning. ----
__global__ void __launch_bounds__(1024) k_post(float* __restrict__ out) {
    const int bx = blockIdx.x;
    const int t = threadIdx.x, lane = t & 31, w = t >> 5;
    if (bx < 32) {
        // single-pass CDF: thread t owns buckets 4t..4t+3
        const int b = bx;
        unsigned* cp = g_cntP + (size_t)b * NBUCK;
        unsigned* cg = g_cntG + (size_t)b * NBUCK;
        float*    sp = g_sumP + (size_t)b * NBUCK;
        float*    sg = g_sumG + (size_t)b * NBUCK;
        uint4 cu4 = reinterpret_cast<uint4*>(cp)[t];
        uint4 cv4 = reinterpret_cast<uint4*>(cg)[t];
        float4 su4 = reinterpret_cast<float4*>(sp)[t];
        float4 sv4 = reinterpret_cast<float4*>(sg)[t];
        int cu[4] = {(int)cu4.x,(int)cu4.y,(int)cu4.z,(int)cu4.w};
        int cv[4] = {(int)cv4.x,(int)cv4.y,(int)cv4.z,(int)cv4.w};
        float su[4] = {su4.x,su4.y,su4.z,su4.w};
        float sv[4] = {sv4.x,sv4.y,sv4.z,sv4.w};
        int pre[4]; int tot = 0;
        #pragma unroll
        for (int j = 0; j < 4; ++j) { pre[j] = tot; tot += cu[j] - cv[j]; }
        __shared__ int wsum[32];
        int x = tot;
        #pragma unroll
        for (int o = 1; o < 32; o <<= 1) {
            int y = __shfl_up_sync(0xffffffffu, x, o);
            if (lane >= o) x += y;
        }
        if (lane == 31) wsum[w] = x;
        __syncthreads();
        if (w == 0) {
            int v = wsum[lane];
            #pragma unroll
            for (int o = 1; o < 32; o <<= 1) {
                int y = __shfl_up_sync(0xffffffffu, v, o);
                if (lane >= o) v += y;
            }
            wsum[lane] = v;
        }
        __syncthreads();
        int texcl = x - tot + (w ? wsum[w-1] : 0);
        double acc = 0.0;
        #pragma unroll
        for (int j = 0; j < 4; ++j) {
            int excl = texcl + pre[j];
            if (((cu[j] | cv[j]) != 0) || (excl != 0)) {
                unsigned kb = (unsigned)(t*4 + j) << 20;
                double L = (double)keydec(kb);
                double R = (double)keydec(kb + 0x100000u);
                acc += fabs((double)excl * (R - L)
                            + (double)cu[j] * R - (double)su[j]
                            - (double)cv[j] * R + (double)sv[j]);
            }
        }
        reinterpret_cast<uint4*>(cp)[t] = make_uint4(0,0,0,0);
        reinterpret_cast<uint4*>(cg)[t] = make_uint4(0,0,0,0);
        reinterpret_cast<float4*>(sp)[t] = make_float4(0.f,0.f,0.f,0.f);
        reinterpret_cast<float4*>(sg)[t] = make_float4(0.f,0.f,0.f,0.f);
        __shared__ double dsm[32];
        #pragma unroll
        for (int o = 16; o; o >>= 1) acc += __shfl_xor_sync(0xffffffffu, acc, o);
        if (lane == 0) dsm[w] = acc;
        __syncthreads();
        if (w == 0) {
            acc = dsm[lane];
            #pragma unroll
            for (int o = 16; o; o >>= 1) acc += __shfl_xor_sync(0xffffffffu, acc, o);
            if (t == 0) g_emd[b] = acc;
        }
    } else if (bx < 40) {
        uint4* m1v = reinterpret_cast<uint4*>(g_m1);
        float s = 0.f;
        for (int i = (bx-32)*1024 + t; i < B_*N_/4; i += 8*1024) {
            uint4 v = m1v[i];
            s += sqrtf(mindec(v.x)) + sqrtf(mindec(v.y))
               + sqrtf(mindec(v.z)) + sqrtf(mindec(v.w));
            m1v[i] = make_uint4(0,0,0,0);
        }
        s = blockReduceSum(s);
        if (t == 0) atomicAdd(&g_s1, (double)s);
    } else {
        uint4* m2v = reinterpret_cast<uint4*>(g_m2);
        float s = 0.f;
        for (int i = (bx-40)*1024 + t; i < N_*N_/4; i += 248*1024) {
            uint4 v = m2v[i];
            s += sqrtf(mindec(v.x)) + sqrtf(mindec(v.y))
               + sqrtf(mindec(v.z)) + sqrtf(mindec(v.w));
            m2v[i] = make_uint4(0,0,0,0);
        }
        s = blockReduceSum(s);
        if (t == 0) atomicAdd(&g_s2, (double)s);
    }

    // last finishing block combines and self-cleans accumulators
    __syncthreads();
    __threadfence();
    __shared__ unsigned amlast;
    if (t == 0) amlast = (atomicAdd(&g_done, 1u) == 287u) ? 1u : 0u;
    __syncthreads();
    if (amlast) {
        if (t < B_) {
            double mae  = g_mae / (double)TOT;
            double cham = g_s1 / (double)(B_*N_) + g_s2 / (double)(N_*N_);
            out[t] = (float)(mae + cham + g_emd[t] / (double)NDF);
        }
        __syncthreads();
        if (t == 0) { g_mae = 0.0; g_s1 = 0.0; g_s2 = 0.0; g_done = 0u; }
    }
}

extern "C" void kernel_launch(void* const* d_in, const int* in_sizes, int n_in,
                              void* d_out, int out_size) {
    const float* pred   = (const float*)d_in[0];
    const float* target = (const float*)d_in[1];
    float* out = (float*)d_out;

    cudaFuncSetAttribute(k_chamfer, cudaFuncAttributeMaxDynamicSharedMemorySize, CHAM_SMEM);
    cudaFuncSetAttribute(k_fused,   cudaFuncAttributeMaxDynamicSharedMemorySize, FUSED_SMEM);

    k_fused<<<256, 512, FUSED_SMEM>>>(pred, target);
    k_chamfer<<<dim3(8, 8, 2), 512, CHAM_SMEM>>>();
    k_post<<<288, 1024>>>(out);
}